// round 12
// baseline (speedup 1.0000x reference)
#include <cuda_runtime.h>
#include <cuda_bf16.h>
#include <math.h>
#include <stdint.h>

// Problem constants (fixed by setup_inputs)
#define BATCH   2
#define SEQ     2048
#define DM      1024
#define NH      16
#define HD      64
#define MTOT    (BATCH * SEQ)      // 4096
#define BH      (BATCH * NH)       // 32

typedef __nv_bfloat16 bf16;

// ---------------- scratch (static device globals; no allocs allowed) -------
__device__ bf16 g_xh[3][(size_t)MTOT * DM];      // split inputs q,k,v
__device__ bf16 g_xl[3][(size_t)MTOT * DM];
__device__ bf16 g_wh[4][(size_t)DM * DM];        // split weights Wq,Wk,Wv,Wo
__device__ bf16 g_wl[4][(size_t)DM * DM];
__device__ bf16 g_Qh[(size_t)BH * SEQ * HD], g_Ql[(size_t)BH * SEQ * HD];
__device__ bf16 g_Kh[(size_t)BH * SEQ * HD], g_Kl[(size_t)BH * SEQ * HD];
__device__ bf16 g_Vh[(size_t)BH * SEQ * HD], g_Vl[(size_t)BH * SEQ * HD];
__device__ bf16 g_Ah[(size_t)MTOT * DM], g_Al[(size_t)MTOT * DM];  // attn out split
__device__ float g_maskbias[MTOT];               // [b][l] -> 0 or -inf

// ======================= helpers ==========================================
__device__ __forceinline__ uint32_t smem_u32(const void* p) {
    uint32_t a;
    asm("{ .reg .u64 t; cvta.to.shared.u64 t, %1; cvt.u32.u64 %0, t; }"
        : "=r"(a) : "l"(p));
    return a;
}

// split fp32 -> (hi, lo) bf16x2 pairs
__device__ __forceinline__ void cvt2_split(float a, float b, uint32_t& h, uint32_t& l) {
    __nv_bfloat162 hh = __floats2bfloat162_rn(a, b);
    float ra = a - __bfloat162float(__low2bfloat16(hh));
    float rb = b - __bfloat162float(__high2bfloat16(hh));
    __nv_bfloat162 ll = __floats2bfloat162_rn(ra, rb);
    h = *reinterpret_cast<uint32_t*>(&hh);
    l = *reinterpret_cast<uint32_t*>(&ll);
}

#define LDMX4(r0, r1, r2, r3, addr)                                           \
    asm volatile("ldmatrix.sync.aligned.m8n8.x4.shared.b16 {%0,%1,%2,%3}, [%4];" \
        : "=r"(r0), "=r"(r1), "=r"(r2), "=r"(r3) : "r"(addr))

#define LDMX4T(r0, r1, r2, r3, addr)                                          \
    asm volatile("ldmatrix.sync.aligned.m8n8.x4.trans.shared.b16 {%0,%1,%2,%3}, [%4];" \
        : "=r"(r0), "=r"(r1), "=r"(r2), "=r"(r3) : "r"(addr))

#define MMA16816(c, a, b)                                                     \
    asm volatile("mma.sync.aligned.m16n8k16.row.col.f32.bf16.bf16.f32 "       \
        "{%0,%1,%2,%3}, {%4,%5,%6,%7}, {%8,%9}, {%0,%1,%2,%3};"               \
        : "+f"((c)[0]), "+f"((c)[1]), "+f"((c)[2]), "+f"((c)[3])              \
        : "r"((a)[0]), "r"((a)[1]), "r"((a)[2]), "r"((a)[3]),                 \
          "r"((b)[0]), "r"((b)[1]))

#define CPA16(dst, src)                                                       \
    asm volatile("cp.async.cg.shared.global [%0], [%1], 16;"                  \
        :: "r"(dst), "l"(src))
#define CPA_COMMIT() asm volatile("cp.async.commit_group;" ::: "memory")
#define CPA_WAIT1()  asm volatile("cp.async.wait_group 1;" ::: "memory")
#define CPA_WAIT0()  asm volatile("cp.async.wait_group 0;" ::: "memory")

// ================== mask dtype sniff + convert to float bias ===============
__global__ __launch_bounds__(1024) void mask_convert(const void* __restrict__ mask)
{
    __shared__ int s_f32, s_u8;
    const unsigned int* w = (const unsigned int*)mask;
    const int tid = threadIdx.x;
    if (tid == 0) { s_f32 = 0; s_u8 = 0; }
    __syncthreads();
    unsigned int x = w[tid];
    if (x == 0x3F800000u) atomicOr(&s_f32, 1);
    else if (x > 1u)      atomicOr(&s_u8, 1);
    __syncthreads();
    const int cls = s_f32 ? 2 : (s_u8 ? 0 : 1);

#pragma unroll
    for (int u = 0; u < 4; u++) {
        int i = tid * 4 + u;
        bool m;
        if (cls == 0)      m = ((const unsigned char*)mask)[i] != 0;
        else if (cls == 1) m = ((const int*)mask)[i] != 0;
        else               m = ((const unsigned int*)mask)[i] != 0u;
        g_maskbias[i] = m ? -INFINITY : 0.f;
    }
}

// ================== fp32 -> split bf16 hi/lo (elementwise) =================
__global__ __launch_bounds__(256) void cvt_split_kernel(
    const float* __restrict__ src, bf16* __restrict__ dh,
    bf16* __restrict__ dl, int n4)
{
    int i = blockIdx.x * blockDim.x + threadIdx.x;
    if (i >= n4) return;
    float4 u = ((const float4*)src)[i];
    uint2 h, l;
    cvt2_split(u.x, u.y, h.x, l.x);
    cvt2_split(u.z, u.w, h.y, l.y);
    ((uint2*)dh)[i] = h;
    ((uint2*)dl)[i] = l;
}

// ========= bf16 GEMM: C = A * B^T + bias (pre-split, cp.async 2-stage) =====
// Ah/Al: [4096,1024] bf16. Bh/Bl: [1024,1024] bf16 (weights [out,in]).
// CTA tile 128x128, BK=32, 8 warps (warp tile 64x32).
#define BK2   32
#define PADK2 40                     // bf16 elems per smem row (80 B)
#define ROWB  (PADK2 * 2)            // 80
#define BUFB  (128 * ROWB)           // 10240
#define STG   (4 * BUFB)             // 40960 per stage (Ah,Al,Bh,Bl)
#define GSMEM (2 * STG)              // 81920

__global__ __launch_bounds__(256, 2) void gemm_bf16(
    const bf16* __restrict__ Ah, const bf16* __restrict__ Al,
    const bf16* __restrict__ Bh, const bf16* __restrict__ Bl,
    const float* __restrict__ bias, float* __restrict__ Cf,
    bf16* __restrict__ Ch, bf16* __restrict__ Cl, int permute)
{
    extern __shared__ char smem[];
    const uint32_t sb = smem_u32(smem);
    const int tid  = threadIdx.x;
    const int wid  = tid >> 5;
    const int lane = tid & 31;
    const int bm = blockIdx.y * 128;
    const int bn = blockIdx.x * 128;
    const int wm = (wid & 1) * 64;
    const int wn = (wid >> 1) * 32;

    const bf16* bufs[4] = {Ah, Al, Bh, Bl};

    // issue cp.async for one stage: 2048 16B chunks, 8 per thread
    auto issue = [&](int stage, int k0) {
#pragma unroll
        for (int i = 0; i < 8; i++) {
            int c   = tid + i * 256;         // 0..2047
            int buf = c >> 9;                // 0..3
            int r   = (c >> 2) & 127;
            int seg = c & 3;                 // 16B = 8 bf16
            int grow = (buf < 2) ? (bm + r) : (bn + r);
            const bf16* src = bufs[buf] + (size_t)grow * DM + k0 + seg * 8;
            uint32_t dst = sb + stage * STG + buf * BUFB + r * ROWB + seg * 16;
            CPA16(dst, src);
        }
        CPA_COMMIT();
    };

    float acc[4][4][4];
#pragma unroll
    for (int i = 0; i < 4; i++)
#pragma unroll
        for (int j = 0; j < 4; j++)
#pragma unroll
            for (int c = 0; c < 4; c++) acc[i][j][c] = 0.f;

    const int lr  = lane & 7;
    const int l8  = (lane >> 3) & 1;
    const int l16 = (lane >> 4) & 1;

    issue(0, 0);
    issue(1, BK2);

    const int NCH = DM / BK2;                // 32
    for (int ch = 0; ch < NCH; ch++) {
        CPA_WAIT1();
        __syncthreads();
        const uint32_t st = sb + (ch & 1) * STG;

#pragma unroll
        for (int ks = 0; ks < 2; ks++) {
            uint32_t aH[4][4], aL[4][4];
#pragma unroll
            for (int mt = 0; mt < 4; mt++) {
                uint32_t off = (uint32_t)(wm + mt * 16 + lr + l8 * 8) * ROWB
                             + (uint32_t)(ks * 16 + l16 * 8) * 2;
                LDMX4(aH[mt][0], aH[mt][1], aH[mt][2], aH[mt][3], st + 0 * BUFB + off);
                LDMX4(aL[mt][0], aL[mt][1], aL[mt][2], aL[mt][3], st + 1 * BUFB + off);
            }
            uint32_t bH[4][2], bL[4][2];
#pragma unroll
            for (int np = 0; np < 2; np++) {
                uint32_t off = (uint32_t)(wn + np * 16 + lr + l16 * 8) * ROWB
                             + (uint32_t)(ks * 16 + l8 * 8) * 2;
                uint32_t r0, r1, r2, r3;
                LDMX4(r0, r1, r2, r3, st + 2 * BUFB + off);
                bH[np * 2][0] = r0; bH[np * 2][1] = r1;
                bH[np * 2 + 1][0] = r2; bH[np * 2 + 1][1] = r3;
                LDMX4(r0, r1, r2, r3, st + 3 * BUFB + off);
                bL[np * 2][0] = r0; bL[np * 2][1] = r1;
                bL[np * 2 + 1][0] = r2; bL[np * 2 + 1][1] = r3;
            }
#pragma unroll
            for (int mt = 0; mt < 4; mt++)
#pragma unroll
                for (int nt = 0; nt < 4; nt++) {
                    MMA16816(acc[mt][nt], aH[mt], bH[nt]);
                    MMA16816(acc[mt][nt], aH[mt], bL[nt]);
                    MMA16816(acc[mt][nt], aL[mt], bH[nt]);
                }
        }
        __syncthreads();                     // all warps done reading stage
        if (ch + 2 < NCH) issue(ch & 1, (ch + 2) * BK2);
    }

    // ---- epilogue ----
    const int crow = lane >> 2;
    const int ccol = (lane & 3) * 2;
#pragma unroll
    for (int mt = 0; mt < 4; mt++) {
#pragma unroll
        for (int nt = 0; nt < 4; nt++) {
            int n0 = bn + wn + nt * 8 + ccol;
            float b0 = bias[n0], b1 = bias[n0 + 1];
#pragma unroll
            for (int half = 0; half < 2; half++) {
                int m = bm + wm + mt * 16 + crow + half * 8;
                float v0 = acc[mt][nt][half * 2 + 0] + b0;
                float v1 = acc[mt][nt][half * 2 + 1] + b1;
                if (!permute) {
                    float2 v; v.x = v0; v.y = v1;
                    *(float2*)(Cf + (size_t)m * DM + n0) = v;
                } else {
                    int b_ = m >> 11;
                    int l  = m & (SEQ - 1);
                    int h  = n0 >> 6;
                    int d  = n0 & (HD - 1);
                    size_t idx = ((size_t)(b_ * NH + h) * SEQ + l) * HD + d;
                    uint32_t hh, ll;
                    cvt2_split(v0, v1, hh, ll);
                    *(uint32_t*)(Ch + idx) = hh;
                    *(uint32_t*)(Cl + idx) = ll;
                }
            }
        }
    }
}

// ============== Flash attention on mma.sync (pre-split bf16) ===============
// Qh/Ql etc: [bh][l][64] bf16. out: split bf16 g_Ah/g_Al [b*l][1024].
#define APAD  72
#define ATILE (64 * APAD * 2)      // 9216 B per operand buffer
#define A_QH  0
#define A_QL  (ATILE)
#define A_KH  (2 * ATILE)
#define A_KL  (3 * ATILE)
#define A_VH  (4 * ATILE)
#define A_VL  (5 * ATILE)
#define A_MS  (6 * ATILE)
#define ATT_SMEM (A_MS + 256)

__global__ __launch_bounds__(128) void attn_mma(
    const bf16* __restrict__ Qh, const bf16* __restrict__ Ql,
    const bf16* __restrict__ Kh, const bf16* __restrict__ Kl,
    const bf16* __restrict__ Vh, const bf16* __restrict__ Vl,
    const float* __restrict__ maskbias,
    bf16* __restrict__ Oh, bf16* __restrict__ Ol)
{
    extern __shared__ char smem[];
    const uint32_t sb = smem_u32(smem);
    float* Ms = (float*)(smem + A_MS);

    const int bh = blockIdx.y;
    const int b_ = bh >> 4;
    const int h  = bh & (NH - 1);
    const int q0 = blockIdx.x * 64;
    const int tid  = threadIdx.x;
    const int wid  = tid >> 5;
    const int lane = tid & 31;
    const int lr  = lane & 7;
    const int l8  = (lane >> 3) & 1;
    const int l16 = (lane >> 4) & 1;
    const int crow = lane >> 2;
    const int ccol = (lane & 3) * 2;
    const float scale = 0.125f;              // 1/sqrt(64)

    // ---- copy Q tile (64x64 bf16, hi+lo) ----
    {
        const bf16* srcs[2] = {Qh + ((size_t)bh * SEQ + q0) * HD,
                               Ql + ((size_t)bh * SEQ + q0) * HD};
        const uint32_t doff[2] = {A_QH, A_QL};
#pragma unroll
        for (int i = 0; i < 8; i++) {
            int c = tid + i * 128;           // 0..1023
            int buf = c >> 9;
            int r   = (c >> 3) & 63;
            int seg = c & 7;
            uint4 v = *(const uint4*)(srcs[buf] + r * HD + seg * 8);
            *(uint4*)(smem + doff[buf] + r * APAD * 2 + seg * 16) = v;
        }
    }

    float O[8][4];
#pragma unroll
    for (int i = 0; i < 8; i++)
#pragma unroll
        for (int j = 0; j < 4; j++) O[i][j] = 0.f;
    float m0 = -INFINITY, m1 = -INFINITY, li0 = 0.f, li1 = 0.f;
    __syncthreads();

    for (int t = 0; t < SEQ / 64; t++) {
        const int k0 = t * 64;
        {
            const bf16* srcs[4] = {Kh + ((size_t)bh * SEQ + k0) * HD,
                                   Kl + ((size_t)bh * SEQ + k0) * HD,
                                   Vh + ((size_t)bh * SEQ + k0) * HD,
                                   Vl + ((size_t)bh * SEQ + k0) * HD};
            const uint32_t doff[4] = {A_KH, A_KL, A_VH, A_VL};
#pragma unroll
            for (int i = 0; i < 16; i++) {
                int c = tid + i * 128;       // 0..2047
                int buf = c >> 9;
                int r   = (c >> 3) & 63;
                int seg = c & 7;
                uint4 v = *(const uint4*)(srcs[buf] + r * HD + seg * 8);
                *(uint4*)(smem + doff[buf] + r * APAD * 2 + seg * 16) = v;
            }
        }
        if (tid < 64) Ms[tid] = maskbias[(size_t)b_ * SEQ + k0 + tid];
        __syncthreads();

        // ---- S = Q * K^T ----
        float S[8][4];
#pragma unroll
        for (int i = 0; i < 8; i++)
#pragma unroll
            for (int j = 0; j < 4; j++) S[i][j] = 0.f;

#pragma unroll
        for (int ks = 0; ks < 4; ks++) {
            uint32_t aH[4], aL[4];
            uint32_t offa = (uint32_t)((wid * 16 + lr + l8 * 8) * APAD
                                       + ks * 16 + l16 * 8) * 2;
            LDMX4(aH[0], aH[1], aH[2], aH[3], sb + A_QH + offa);
            LDMX4(aL[0], aL[1], aL[2], aL[3], sb + A_QL + offa);
            uint32_t bH[8][2], bL[8][2];
#pragma unroll
            for (int np = 0; np < 4; np++) {
                uint32_t offb = (uint32_t)((np * 16 + lr + l16 * 8) * APAD
                                           + ks * 16 + l8 * 8) * 2;
                uint32_t r0, r1, r2, r3;
                LDMX4(r0, r1, r2, r3, sb + A_KH + offb);
                bH[np * 2][0] = r0; bH[np * 2][1] = r1;
                bH[np * 2 + 1][0] = r2; bH[np * 2 + 1][1] = r3;
                LDMX4(r0, r1, r2, r3, sb + A_KL + offb);
                bL[np * 2][0] = r0; bL[np * 2][1] = r1;
                bL[np * 2 + 1][0] = r2; bL[np * 2 + 1][1] = r3;
            }
#pragma unroll
            for (int nt = 0; nt < 8; nt++) {
                MMA16816(S[nt], aH, bH[nt]);
                MMA16816(S[nt], aH, bL[nt]);
                MMA16816(S[nt], aL, bH[nt]);
            }
        }

        // ---- softmax ----
        float rm0 = -INFINITY, rm1 = -INFINITY;
#pragma unroll
        for (int nt = 0; nt < 8; nt++) {
            float mk0 = Ms[nt * 8 + ccol], mk1 = Ms[nt * 8 + ccol + 1];
            S[nt][0] = S[nt][0] * scale + mk0;
            S[nt][1] = S[nt][1] * scale + mk1;
            S[nt][2] = S[nt][2] * scale + mk0;
            S[nt][3] = S[nt][3] * scale + mk1;
            rm0 = fmaxf(rm0, fmaxf(S[nt][0], S[nt][1]));
            rm1 = fmaxf(rm1, fmaxf(S[nt][2], S[nt][3]));
        }
        rm0 = fmaxf(rm0, __shfl_xor_sync(0xffffffffu, rm0, 1));
        rm0 = fmaxf(rm0, __shfl_xor_sync(0xffffffffu, rm0, 2));
        rm1 = fmaxf(rm1, __shfl_xor_sync(0xffffffffu, rm1, 1));
        rm1 = fmaxf(rm1, __shfl_xor_sync(0xffffffffu, rm1, 2));

        float mn0 = fmaxf(m0, rm0), mn1 = fmaxf(m1, rm1);
        float ms0 = fmaxf(mn0, -1e30f), ms1 = fmaxf(mn1, -1e30f);
        float al0 = __expf(m0 - ms0), al1 = __expf(m1 - ms1);
        m0 = mn0; m1 = mn1;

        float rs0 = 0.f, rs1 = 0.f;
        uint32_t pH[4][4], pL[4][4];
#pragma unroll
        for (int nt = 0; nt < 8; nt++) {
            float p0 = __expf(S[nt][0] - ms0);
            float p1 = __expf(S[nt][1] - ms0);
            float p2 = __expf(S[nt][2] - ms1);
            float p3 = __expf(S[nt][3] - ms1);
            rs0 += p0 + p1; rs1 += p2 + p3;
            int ks2 = nt >> 1, base = (nt & 1) * 2;
            uint32_t h01, l01, h23, l23;
            cvt2_split(p0, p1, h01, l01);
            cvt2_split(p2, p3, h23, l23);
            pH[ks2][base] = h01; pH[ks2][base + 1] = h23;
            pL[ks2][base] = l01; pL[ks2][base + 1] = l23;
        }
        rs0 += __shfl_xor_sync(0xffffffffu, rs0, 1);
        rs0 += __shfl_xor_sync(0xffffffffu, rs0, 2);
        rs1 += __shfl_xor_sync(0xffffffffu, rs1, 1);
        rs1 += __shfl_xor_sync(0xffffffffu, rs1, 2);
        li0 = li0 * al0 + rs0;
        li1 = li1 * al1 + rs1;
#pragma unroll
        for (int nt = 0; nt < 8; nt++) {
            O[nt][0] *= al0; O[nt][1] *= al0;
            O[nt][2] *= al1; O[nt][3] *= al1;
        }

        // ---- O += P * V ----
#pragma unroll
        for (int ks2 = 0; ks2 < 4; ks2++) {
            uint32_t bH2[8][2], bL2[8][2];
#pragma unroll
            for (int np = 0; np < 4; np++) {
                uint32_t offv = (uint32_t)((ks2 * 16 + lr + l8 * 8) * APAD
                                           + np * 16 + l16 * 8) * 2;
                uint32_t r0, r1, r2, r3;
                LDMX4T(r0, r1, r2, r3, sb + A_VH + offv);
                bH2[np * 2][0] = r0; bH2[np * 2][1] = r1;
                bH2[np * 2 + 1][0] = r2; bH2[np * 2 + 1][1] = r3;
                LDMX4T(r0, r1, r2, r3, sb + A_VL + offv);
                bL2[np * 2][0] = r0; bL2[np * 2][1] = r1;
                bL2[np * 2 + 1][0] = r2; bL2[np * 2 + 1][1] = r3;
            }
#pragma unroll
            for (int nt = 0; nt < 8; nt++) {
                MMA16816(O[nt], pH[ks2], bH2[nt]);
                MMA16816(O[nt], pH[ks2], bL2[nt]);
                MMA16816(O[nt], pL[ks2], bH2[nt]);
            }
        }
        __syncthreads();
    }

    // ---- normalize + split-write out[b][l][h*64 + d] ----
    float inv0 = 1.f / li0, inv1 = 1.f / li1;
    int l0 = q0 + wid * 16 + crow;
    size_t base0 = ((size_t)b_ * SEQ + l0) * DM + h * HD;
    size_t base1 = base0 + (size_t)8 * DM;
#pragma unroll
    for (int nt = 0; nt < 8; nt++) {
        int col = nt * 8 + ccol;
        uint32_t hh, ll;
        cvt2_split(O[nt][0] * inv0, O[nt][1] * inv0, hh, ll);
        *(uint32_t*)(Oh + base0 + col) = hh;
        *(uint32_t*)(Ol + base0 + col) = ll;
        cvt2_split(O[nt][2] * inv1, O[nt][3] * inv1, hh, ll);
        *(uint32_t*)(Oh + base1 + col) = hh;
        *(uint32_t*)(Ol + base1 + col) = ll;
    }
}

// ================================ launch ===================================
extern "C" void kernel_launch(void* const* d_in, const int* in_sizes, int n_in,
                              void* d_out, int out_size)
{
    const float* q    = (const float*)d_in[0];
    const float* k    = (const float*)d_in[1];
    const float* v    = (const float*)d_in[2];
    const void*  mask = (const void*)d_in[3];
    const float* Wq = (const float*)d_in[4];
    const float* bq = (const float*)d_in[5];
    const float* Wk = (const float*)d_in[6];
    const float* bk = (const float*)d_in[7];
    const float* Wv = (const float*)d_in[8];
    const float* bv = (const float*)d_in[9];
    const float* Wo = (const float*)d_in[10];
    const float* bo = (const float*)d_in[11];

    bf16 *xh, *xl, *wh, *wl;
    bf16 *Qh, *Ql, *Kh, *Kl, *Vh, *Vl, *Ah, *Al;
    float* pM;
    cudaGetSymbolAddress((void**)&xh, g_xh);
    cudaGetSymbolAddress((void**)&xl, g_xl);
    cudaGetSymbolAddress((void**)&wh, g_wh);
    cudaGetSymbolAddress((void**)&wl, g_wl);
    cudaGetSymbolAddress((void**)&Qh, g_Qh);
    cudaGetSymbolAddress((void**)&Ql, g_Ql);
    cudaGetSymbolAddress((void**)&Kh, g_Kh);
    cudaGetSymbolAddress((void**)&Kl, g_Kl);
    cudaGetSymbolAddress((void**)&Vh, g_Vh);
    cudaGetSymbolAddress((void**)&Vl, g_Vl);
    cudaGetSymbolAddress((void**)&Ah, g_Ah);
    cudaGetSymbolAddress((void**)&Al, g_Al);
    cudaGetSymbolAddress((void**)&pM, g_maskbias);

    cudaFuncSetAttribute(gemm_bf16, cudaFuncAttributeMaxDynamicSharedMemorySize,
                         GSMEM);
    cudaFuncSetAttribute(attn_mma, cudaFuncAttributeMaxDynamicSharedMemorySize,
                         ATT_SMEM);

    mask_convert<<<1, 1024>>>(mask);

    // pre-split all fp32 operands into bf16 hi/lo
    const size_t NX = (size_t)MTOT * DM;     // 4M
    const size_t NW = (size_t)DM * DM;       // 1M
    cvt_split_kernel<<<(int)(NX / 4 / 256), 256>>>(q,  xh + 0 * NX, xl + 0 * NX, (int)(NX / 4));
    cvt_split_kernel<<<(int)(NX / 4 / 256), 256>>>(k,  xh + 1 * NX, xl + 1 * NX, (int)(NX / 4));
    cvt_split_kernel<<<(int)(NX / 4 / 256), 256>>>(v,  xh + 2 * NX, xl + 2 * NX, (int)(NX / 4));
    cvt_split_kernel<<<(int)(NW / 4 / 256), 256>>>(Wq, wh + 0 * NW, wl + 0 * NW, (int)(NW / 4));
    cvt_split_kernel<<<(int)(NW / 4 / 256), 256>>>(Wk, wh + 1 * NW, wl + 1 * NW, (int)(NW / 4));
    cvt_split_kernel<<<(int)(NW / 4 / 256), 256>>>(Wv, wh + 2 * NW, wl + 2 * NW, (int)(NW / 4));
    cvt_split_kernel<<<(int)(NW / 4 / 256), 256>>>(Wo, wh + 3 * NW, wl + 3 * NW, (int)(NW / 4));

    dim3 ggrid(DM / 128, MTOT / 128);       // (8, 32)
    gemm_bf16<<<ggrid, 256, GSMEM>>>(xh + 0 * NX, xl + 0 * NX, wh + 0 * NW, wl + 0 * NW,
                                     bq, nullptr, Qh, Ql, 1);
    gemm_bf16<<<ggrid, 256, GSMEM>>>(xh + 1 * NX, xl + 1 * NX, wh + 1 * NW, wl + 1 * NW,
                                     bk, nullptr, Kh, Kl, 1);
    gemm_bf16<<<ggrid, 256, GSMEM>>>(xh + 2 * NX, xl + 2 * NX, wh + 2 * NW, wl + 2 * NW,
                                     bv, nullptr, Vh, Vl, 1);

    dim3 agrid(SEQ / 64, BH);               // (32, 32)
    attn_mma<<<agrid, 128, ATT_SMEM>>>(Qh, Ql, Kh, Kl, Vh, Vl, pM, Ah, Al);

    gemm_bf16<<<ggrid, 256, GSMEM>>>(Ah, Al, wh + 3 * NW, wl + 3 * NW,
                                     bo, (float*)d_out, nullptr, nullptr, 0);
}

// round 13
// speedup vs baseline: 1.0075x; 1.0075x over previous
#include <cuda_runtime.h>
#include <cuda_bf16.h>
#include <math.h>
#include <stdint.h>

// Problem constants (fixed by setup_inputs)
#define BATCH   2
#define SEQ     2048
#define DM      1024
#define NH      16
#define HD      64
#define MTOT    (BATCH * SEQ)      // 4096
#define BH      (BATCH * NH)       // 32

typedef __nv_bfloat16 bf16;

// ---------------- scratch (static device globals; no allocs allowed) -------
__device__ bf16 g_xh[3][(size_t)MTOT * DM];      // split inputs q,k,v
__device__ bf16 g_xl[3][(size_t)MTOT * DM];
__device__ bf16 g_wh[4][(size_t)DM * DM];        // split weights Wq,Wk,Wv,Wo
__device__ bf16 g_wl[4][(size_t)DM * DM];
__device__ bf16 g_Qh[(size_t)BH * SEQ * HD], g_Ql[(size_t)BH * SEQ * HD];
__device__ bf16 g_Kh[(size_t)BH * SEQ * HD], g_Kl[(size_t)BH * SEQ * HD];
__device__ bf16 g_Vh[(size_t)BH * SEQ * HD], g_Vl[(size_t)BH * SEQ * HD];
__device__ bf16 g_Ah[(size_t)MTOT * DM], g_Al[(size_t)MTOT * DM];  // attn out
__device__ float g_maskbias[MTOT];               // [b][l] -> 0 or -inf

// ======================= helpers ==========================================
__device__ __forceinline__ uint32_t smem_u32(const void* p) {
    uint32_t a;
    asm("{ .reg .u64 t; cvta.to.shared.u64 t, %1; cvt.u32.u64 %0, t; }"
        : "=r"(a) : "l"(p));
    return a;
}

// split fp32 -> (hi, lo) bf16x2 pairs
__device__ __forceinline__ void cvt2_split(float a, float b, uint32_t& h, uint32_t& l) {
    __nv_bfloat162 hh = __floats2bfloat162_rn(a, b);
    float ra = a - __bfloat162float(__low2bfloat16(hh));
    float rb = b - __bfloat162float(__high2bfloat16(hh));
    __nv_bfloat162 ll = __floats2bfloat162_rn(ra, rb);
    h = *reinterpret_cast<uint32_t*>(&hh);
    l = *reinterpret_cast<uint32_t*>(&ll);
}

#define LDMX4(r0, r1, r2, r3, addr)                                           \
    asm volatile("ldmatrix.sync.aligned.m8n8.x4.shared.b16 {%0,%1,%2,%3}, [%4];" \
        : "=r"(r0), "=r"(r1), "=r"(r2), "=r"(r3) : "r"(addr))

#define LDMX4T(r0, r1, r2, r3, addr)                                          \
    asm volatile("ldmatrix.sync.aligned.m8n8.x4.trans.shared.b16 {%0,%1,%2,%3}, [%4];" \
        : "=r"(r0), "=r"(r1), "=r"(r2), "=r"(r3) : "r"(addr))

#define MMA16816(c, a, b)                                                     \
    asm volatile("mma.sync.aligned.m16n8k16.row.col.f32.bf16.bf16.f32 "       \
        "{%0,%1,%2,%3}, {%4,%5,%6,%7}, {%8,%9}, {%0,%1,%2,%3};"               \
        : "+f"((c)[0]), "+f"((c)[1]), "+f"((c)[2]), "+f"((c)[3])              \
        : "r"((a)[0]), "r"((a)[1]), "r"((a)[2]), "r"((a)[3]),                 \
          "r"((b)[0]), "r"((b)[1]))

// ================== mask dtype sniff + convert to float bias ===============
__global__ __launch_bounds__(1024) void mask_convert(const void* __restrict__ mask)
{
    __shared__ int s_f32, s_u8;
    const unsigned int* w = (const unsigned int*)mask;
    const int tid = threadIdx.x;
    if (tid == 0) { s_f32 = 0; s_u8 = 0; }
    __syncthreads();
    unsigned int x = w[tid];
    if (x == 0x3F800000u) atomicOr(&s_f32, 1);
    else if (x > 1u)      atomicOr(&s_u8, 1);
    __syncthreads();
    const int cls = s_f32 ? 2 : (s_u8 ? 0 : 1);

#pragma unroll
    for (int u = 0; u < 4; u++) {
        int i = tid * 4 + u;
        bool m;
        if (cls == 0)      m = ((const unsigned char*)mask)[i] != 0;
        else if (cls == 1) m = ((const int*)mask)[i] != 0;
        else               m = ((const unsigned int*)mask)[i] != 0u;
        g_maskbias[i] = m ? -INFINITY : 0.f;
    }
}

// ================== fp32 -> split bf16 hi/lo (elementwise) =================
__global__ __launch_bounds__(256) void cvt_split_kernel(
    const float* __restrict__ src, bf16* __restrict__ dh,
    bf16* __restrict__ dl, int n4)
{
    int i = blockIdx.x * blockDim.x + threadIdx.x;
    if (i >= n4) return;
    float4 u = ((const float4*)src)[i];
    uint2 h, l;
    cvt2_split(u.x, u.y, h.x, l.x);
    cvt2_split(u.z, u.w, h.y, l.y);
    ((uint2*)dh)[i] = h;
    ((uint2*)dl)[i] = l;
}

// ====== pre-split bf16 GEMM: C = A * B^T + bias (BK=64, single-buffer) =====
// CTA tile 128x128, 8 warps (warp tile 64x32), 3 MMAs per product term.
#define PADK   72                    // bf16 elems per smem row (+8 pad)
#define TILEB  (128 * PADK * 2)      // 18432 B per operand buffer
#define GEMM_SMEM (4 * TILEB)        // 73728 B (AHI, ALO, BHI, BLO)

__global__ __launch_bounds__(256, 2) void gemm_ps(
    const bf16* __restrict__ Ah, const bf16* __restrict__ Al,
    const bf16* __restrict__ Bh, const bf16* __restrict__ Bl,
    const float* __restrict__ bias, float* __restrict__ Cf,
    bf16* __restrict__ Ch, bf16* __restrict__ Cl, int permute)
{
    extern __shared__ char smem[];
    const uint32_t sb = smem_u32(smem);
    const int tid  = threadIdx.x;
    const int wid  = tid >> 5;
    const int lane = tid & 31;
    const int bm = blockIdx.y * 128;
    const int bn = blockIdx.x * 128;
    const int wm = (wid & 1) * 64;
    const int wn = (wid >> 1) * 32;

    const bf16* bufs[4] = {Ah, Al, Bh, Bl};

    float acc[4][4][4];
#pragma unroll
    for (int i = 0; i < 4; i++)
#pragma unroll
        for (int j = 0; j < 4; j++)
#pragma unroll
            for (int c = 0; c < 4; c++) acc[i][j][c] = 0.f;

    const int lr  = lane & 7;
    const int l8  = (lane >> 3) & 1;
    const int l16 = (lane >> 4) & 1;

    for (int k0 = 0; k0 < DM; k0 += 64) {
        // ---- fill 4 buffers (128 x 64 bf16 each), plain uint4 copies ----
#pragma unroll
        for (int i = 0; i < 16; i++) {
            int c   = tid + i * 256;         // 0..4095
            int buf = c >> 10;               // 0..3
            int r   = (c >> 3) & 127;
            int seg = c & 7;                 // 8 bf16 = 16 B
            int grow = ((buf < 2) ? bm : bn) + r;
            uint4 v = *(const uint4*)(bufs[buf] + (size_t)grow * DM + k0 + seg * 8);
            *(uint4*)(smem + buf * TILEB + (r * PADK + seg * 8) * 2) = v;
        }
        __syncthreads();

#pragma unroll
        for (int ks = 0; ks < 4; ks++) {
            uint32_t aH[4][4], aL[4][4];
#pragma unroll
            for (int mt = 0; mt < 4; mt++) {
                uint32_t off = (uint32_t)((wm + mt * 16 + lr + l8 * 8) * PADK
                                          + ks * 16 + l16 * 8) * 2;
                LDMX4(aH[mt][0], aH[mt][1], aH[mt][2], aH[mt][3], sb + 0 * TILEB + off);
                LDMX4(aL[mt][0], aL[mt][1], aL[mt][2], aL[mt][3], sb + 1 * TILEB + off);
            }
            uint32_t bH[4][2], bL[4][2];
#pragma unroll
            for (int np = 0; np < 2; np++) {
                uint32_t off = (uint32_t)((wn + np * 16 + lr + l16 * 8) * PADK
                                          + ks * 16 + l8 * 8) * 2;
                uint32_t r0, r1, r2, r3;
                LDMX4(r0, r1, r2, r3, sb + 2 * TILEB + off);
                bH[np * 2][0] = r0; bH[np * 2][1] = r1;
                bH[np * 2 + 1][0] = r2; bH[np * 2 + 1][1] = r3;
                LDMX4(r0, r1, r2, r3, sb + 3 * TILEB + off);
                bL[np * 2][0] = r0; bL[np * 2][1] = r1;
                bL[np * 2 + 1][0] = r2; bL[np * 2 + 1][1] = r3;
            }
#pragma unroll
            for (int mt = 0; mt < 4; mt++)
#pragma unroll
                for (int nt = 0; nt < 4; nt++) {
                    MMA16816(acc[mt][nt], aH[mt], bH[nt]);
                    MMA16816(acc[mt][nt], aH[mt], bL[nt]);
                    MMA16816(acc[mt][nt], aL[mt], bH[nt]);
                }
        }
        __syncthreads();
    }

    // ---- epilogue ----
    const int crow = lane >> 2;
    const int ccol = (lane & 3) * 2;
#pragma unroll
    for (int mt = 0; mt < 4; mt++) {
#pragma unroll
        for (int nt = 0; nt < 4; nt++) {
            int n0 = bn + wn + nt * 8 + ccol;
            float b0 = bias[n0], b1 = bias[n0 + 1];
#pragma unroll
            for (int half = 0; half < 2; half++) {
                int m = bm + wm + mt * 16 + crow + half * 8;
                float v0 = acc[mt][nt][half * 2 + 0] + b0;
                float v1 = acc[mt][nt][half * 2 + 1] + b1;
                if (!permute) {
                    float2 v; v.x = v0; v.y = v1;
                    *(float2*)(Cf + (size_t)m * DM + n0) = v;
                } else {
                    int b_ = m >> 11;
                    int l  = m & (SEQ - 1);
                    int h  = n0 >> 6;
                    int d  = n0 & (HD - 1);
                    size_t idx = ((size_t)(b_ * NH + h) * SEQ + l) * HD + d;
                    uint32_t hh, ll;
                    cvt2_split(v0, v1, hh, ll);
                    *(uint32_t*)(Ch + idx) = hh;
                    *(uint32_t*)(Cl + idx) = ll;
                }
            }
        }
    }
}

// ============== Flash attention on mma.sync (pre-split bf16) ===============
// BM=128 q-rows/CTA (8 warps x 16 rows), BN=64 kv per tile.
#define APAD  72
#define AQTI  (128 * APAD * 2)     // 18432 B (Q buffers: 128 rows)
#define AKTI  (64 * APAD * 2)      // 9216 B  (K/V buffers: 64 rows)
#define A_QH  0
#define A_QL  (AQTI)
#define A_KH  (2 * AQTI)
#define A_KL  (2 * AQTI + AKTI)
#define A_VH  (2 * AQTI + 2 * AKTI)
#define A_VL  (2 * AQTI + 3 * AKTI)
#define A_MS  (2 * AQTI + 4 * AKTI)
#define ATT_SMEM (A_MS + 256)      // 74 KB

__global__ __launch_bounds__(256) void attn_mma(
    const bf16* __restrict__ Qh, const bf16* __restrict__ Ql,
    const bf16* __restrict__ Kh, const bf16* __restrict__ Kl,
    const bf16* __restrict__ Vh, const bf16* __restrict__ Vl,
    const float* __restrict__ maskbias,
    bf16* __restrict__ Oh, bf16* __restrict__ Ol)
{
    extern __shared__ char smem[];
    const uint32_t sb = smem_u32(smem);
    float* Ms = (float*)(smem + A_MS);

    const int bh = blockIdx.y;
    const int b_ = bh >> 4;
    const int h  = bh & (NH - 1);
    const int q0 = blockIdx.x * 128;
    const int tid  = threadIdx.x;
    const int wid  = tid >> 5;               // 0..7 -> q-rows [wid*16, wid*16+16)
    const int lane = tid & 31;
    const int lr  = lane & 7;
    const int l8  = (lane >> 3) & 1;
    const int l16 = (lane >> 4) & 1;
    const int crow = lane >> 2;
    const int ccol = (lane & 3) * 2;
    const float scale = 0.125f;              // 1/sqrt(64)

    // ---- copy Q tile (128x64 bf16, hi+lo) ----
    {
        const bf16* srcs[2] = {Qh + ((size_t)bh * SEQ + q0) * HD,
                               Ql + ((size_t)bh * SEQ + q0) * HD};
        const uint32_t doff[2] = {A_QH, A_QL};
#pragma unroll
        for (int i = 0; i < 8; i++) {
            int c = tid + i * 256;           // 0..2047
            int buf = c >> 10;
            int r   = (c >> 3) & 127;
            int seg = c & 7;
            uint4 v = *(const uint4*)(srcs[buf] + r * HD + seg * 8);
            *(uint4*)(smem + doff[buf] + r * APAD * 2 + seg * 16) = v;
        }
    }

    float O[8][4];
#pragma unroll
    for (int i = 0; i < 8; i++)
#pragma unroll
        for (int j = 0; j < 4; j++) O[i][j] = 0.f;
    float m0 = -INFINITY, m1 = -INFINITY, li0 = 0.f, li1 = 0.f;
    __syncthreads();

    for (int t = 0; t < SEQ / 64; t++) {
        const int k0 = t * 64;
        {
            const bf16* srcs[4] = {Kh + ((size_t)bh * SEQ + k0) * HD,
                                   Kl + ((size_t)bh * SEQ + k0) * HD,
                                   Vh + ((size_t)bh * SEQ + k0) * HD,
                                   Vl + ((size_t)bh * SEQ + k0) * HD};
            const uint32_t doff[4] = {A_KH, A_KL, A_VH, A_VL};
#pragma unroll
            for (int i = 0; i < 8; i++) {
                int c = tid + i * 256;       // 0..2047
                int buf = c >> 9;
                int r   = (c >> 3) & 63;
                int seg = c & 7;
                uint4 v = *(const uint4*)(srcs[buf] + r * HD + seg * 8);
                *(uint4*)(smem + doff[buf] + r * APAD * 2 + seg * 16) = v;
            }
        }
        if (tid < 64) Ms[tid] = maskbias[(size_t)b_ * SEQ + k0 + tid];
        __syncthreads();

        // ---- S = Q * K^T (warp: 16 q-rows x 64 kv) ----
        float S[8][4];
#pragma unroll
        for (int i = 0; i < 8; i++)
#pragma unroll
            for (int j = 0; j < 4; j++) S[i][j] = 0.f;

#pragma unroll
        for (int ks = 0; ks < 4; ks++) {
            uint32_t aH[4], aL[4];
            uint32_t offa = (uint32_t)((wid * 16 + lr + l8 * 8) * APAD
                                       + ks * 16 + l16 * 8) * 2;
            LDMX4(aH[0], aH[1], aH[2], aH[3], sb + A_QH + offa);
            LDMX4(aL[0], aL[1], aL[2], aL[3], sb + A_QL + offa);
            uint32_t bH[8][2], bL[8][2];
#pragma unroll
            for (int np = 0; np < 4; np++) {
                uint32_t offb = (uint32_t)((np * 16 + lr + l16 * 8) * APAD
                                           + ks * 16 + l8 * 8) * 2;
                uint32_t r0, r1, r2, r3;
                LDMX4(r0, r1, r2, r3, sb + A_KH + offb);
                bH[np * 2][0] = r0; bH[np * 2][1] = r1;
                bH[np * 2 + 1][0] = r2; bH[np * 2 + 1][1] = r3;
                LDMX4(r0, r1, r2, r3, sb + A_KL + offb);
                bL[np * 2][0] = r0; bL[np * 2][1] = r1;
                bL[np * 2 + 1][0] = r2; bL[np * 2 + 1][1] = r3;
            }
#pragma unroll
            for (int nt = 0; nt < 8; nt++) {
                MMA16816(S[nt], aH, bH[nt]);
                MMA16816(S[nt], aH, bL[nt]);
                MMA16816(S[nt], aL, bH[nt]);
            }
        }

        // ---- softmax ----
        float rm0 = -INFINITY, rm1 = -INFINITY;
#pragma unroll
        for (int nt = 0; nt < 8; nt++) {
            float mk0 = Ms[nt * 8 + ccol], mk1 = Ms[nt * 8 + ccol + 1];
            S[nt][0] = S[nt][0] * scale + mk0;
            S[nt][1] = S[nt][1] * scale + mk1;
            S[nt][2] = S[nt][2] * scale + mk0;
            S[nt][3] = S[nt][3] * scale + mk1;
            rm0 = fmaxf(rm0, fmaxf(S[nt][0], S[nt][1]));
            rm1 = fmaxf(rm1, fmaxf(S[nt][2], S[nt][3]));
        }
        rm0 = fmaxf(rm0, __shfl_xor_sync(0xffffffffu, rm0, 1));
        rm0 = fmaxf(rm0, __shfl_xor_sync(0xffffffffu, rm0, 2));
        rm1 = fmaxf(rm1, __shfl_xor_sync(0xffffffffu, rm1, 1));
        rm1 = fmaxf(rm1, __shfl_xor_sync(0xffffffffu, rm1, 2));

        float mn0 = fmaxf(m0, rm0), mn1 = fmaxf(m1, rm1);
        float ms0 = fmaxf(mn0, -1e30f), ms1 = fmaxf(mn1, -1e30f);
        float al0 = __expf(m0 - ms0), al1 = __expf(m1 - ms1);
        m0 = mn0; m1 = mn1;

        float rs0 = 0.f, rs1 = 0.f;
        uint32_t pH[4][4], pL[4][4];
#pragma unroll
        for (int nt = 0; nt < 8; nt++) {
            float p0 = __expf(S[nt][0] - ms0);
            float p1 = __expf(S[nt][1] - ms0);
            float p2 = __expf(S[nt][2] - ms1);
            float p3 = __expf(S[nt][3] - ms1);
            rs0 += p0 + p1; rs1 += p2 + p3;
            int ks2 = nt >> 1, base = (nt & 1) * 2;
            uint32_t h01, l01, h23, l23;
            cvt2_split(p0, p1, h01, l01);
            cvt2_split(p2, p3, h23, l23);
            pH[ks2][base] = h01; pH[ks2][base + 1] = h23;
            pL[ks2][base] = l01; pL[ks2][base + 1] = l23;
        }
        rs0 += __shfl_xor_sync(0xffffffffu, rs0, 1);
        rs0 += __shfl_xor_sync(0xffffffffu, rs0, 2);
        rs1 += __shfl_xor_sync(0xffffffffu, rs1, 1);
        rs1 += __shfl_xor_sync(0xffffffffu, rs1, 2);
        li0 = li0 * al0 + rs0;
        li1 = li1 * al1 + rs1;
#pragma unroll
        for (int nt = 0; nt < 8; nt++) {
            O[nt][0] *= al0; O[nt][1] *= al0;
            O[nt][2] *= al1; O[nt][3] *= al1;
        }

        // ---- O += P * V ----
#pragma unroll
        for (int ks2 = 0; ks2 < 4; ks2++) {
            uint32_t bH2[8][2], bL2[8][2];
#pragma unroll
            for (int np = 0; np < 4; np++) {
                uint32_t offv = (uint32_t)((ks2 * 16 + lr + l8 * 8) * APAD
                                           + np * 16 + l16 * 8) * 2;
                uint32_t r0, r1, r2, r3;
                LDMX4T(r0, r1, r2, r3, sb + A_VH + offv);
                bH2[np * 2][0] = r0; bH2[np * 2][1] = r1;
                bH2[np * 2 + 1][0] = r2; bH2[np * 2 + 1][1] = r3;
                LDMX4T(r0, r1, r2, r3, sb + A_VL + offv);
                bL2[np * 2][0] = r0; bL2[np * 2][1] = r1;
                bL2[np * 2 + 1][0] = r2; bL2[np * 2 + 1][1] = r3;
            }
#pragma unroll
            for (int nt = 0; nt < 8; nt++) {
                MMA16816(O[nt], pH[ks2], bH2[nt]);
                MMA16816(O[nt], pH[ks2], bL2[nt]);
                MMA16816(O[nt], pL[ks2], bH2[nt]);
            }
        }
        __syncthreads();
    }

    // ---- normalize + split-write out[b][l][h*64 + d] ----
    float inv0 = 1.f / li0, inv1 = 1.f / li1;
    int l0 = q0 + wid * 16 + crow;
    size_t base0 = ((size_t)b_ * SEQ + l0) * DM + h * HD;
    size_t base1 = base0 + (size_t)8 * DM;
#pragma unroll
    for (int nt = 0; nt < 8; nt++) {
        int col = nt * 8 + ccol;
        uint32_t hh, ll;
        cvt2_split(O[nt][0] * inv0, O[nt][1] * inv0, hh, ll);
        *(uint32_t*)(Oh + base0 + col) = hh;
        *(uint32_t*)(Ol + base0 + col) = ll;
        cvt2_split(O[nt][2] * inv1, O[nt][3] * inv1, hh, ll);
        *(uint32_t*)(Oh + base1 + col) = hh;
        *(uint32_t*)(Ol + base1 + col) = ll;
    }
}

// ================================ launch ===================================
extern "C" void kernel_launch(void* const* d_in, const int* in_sizes, int n_in,
                              void* d_out, int out_size)
{
    const float* q    = (const float*)d_in[0];
    const float* k    = (const float*)d_in[1];
    const float* v    = (const float*)d_in[2];
    const void*  mask = (const void*)d_in[3];
    const float* Wq = (const float*)d_in[4];
    const float* bq = (const float*)d_in[5];
    const float* Wk = (const float*)d_in[6];
    const float* bk = (const float*)d_in[7];
    const float* Wv = (const float*)d_in[8];
    const float* bv = (const float*)d_in[9];
    const float* Wo = (const float*)d_in[10];
    const float* bo = (const float*)d_in[11];

    bf16 *xh, *xl, *wh, *wl;
    bf16 *Qh, *Ql, *Kh, *Kl, *Vh, *Vl, *Ah, *Al;
    float* pM;
    cudaGetSymbolAddress((void**)&xh, g_xh);
    cudaGetSymbolAddress((void**)&xl, g_xl);
    cudaGetSymbolAddress((void**)&wh, g_wh);
    cudaGetSymbolAddress((void**)&wl, g_wl);
    cudaGetSymbolAddress((void**)&Qh, g_Qh);
    cudaGetSymbolAddress((void**)&Ql, g_Ql);
    cudaGetSymbolAddress((void**)&Kh, g_Kh);
    cudaGetSymbolAddress((void**)&Kl, g_Kl);
    cudaGetSymbolAddress((void**)&Vh, g_Vh);
    cudaGetSymbolAddress((void**)&Vl, g_Vl);
    cudaGetSymbolAddress((void**)&Ah, g_Ah);
    cudaGetSymbolAddress((void**)&Al, g_Al);
    cudaGetSymbolAddress((void**)&pM, g_maskbias);

    cudaFuncSetAttribute(gemm_ps, cudaFuncAttributeMaxDynamicSharedMemorySize,
                         GEMM_SMEM);
    cudaFuncSetAttribute(attn_mma, cudaFuncAttributeMaxDynamicSharedMemorySize,
                         ATT_SMEM);

    mask_convert<<<1, 1024>>>(mask);

    // pre-split all fp32 operands into bf16 hi/lo
    const size_t NX = (size_t)MTOT * DM;     // 4M
    const size_t NW = (size_t)DM * DM;       // 1M
    cvt_split_kernel<<<(int)(NX / 4 / 256), 256>>>(q,  xh + 0 * NX, xl + 0 * NX, (int)(NX / 4));
    cvt_split_kernel<<<(int)(NX / 4 / 256), 256>>>(k,  xh + 1 * NX, xl + 1 * NX, (int)(NX / 4));
    cvt_split_kernel<<<(int)(NX / 4 / 256), 256>>>(v,  xh + 2 * NX, xl + 2 * NX, (int)(NX / 4));
    cvt_split_kernel<<<(int)(NW / 4 / 256), 256>>>(Wq, wh + 0 * NW, wl + 0 * NW, (int)(NW / 4));
    cvt_split_kernel<<<(int)(NW / 4 / 256), 256>>>(Wk, wh + 1 * NW, wl + 1 * NW, (int)(NW / 4));
    cvt_split_kernel<<<(int)(NW / 4 / 256), 256>>>(Wv, wh + 2 * NW, wl + 2 * NW, (int)(NW / 4));
    cvt_split_kernel<<<(int)(NW / 4 / 256), 256>>>(Wo, wh + 3 * NW, wl + 3 * NW, (int)(NW / 4));

    dim3 ggrid(DM / 128, MTOT / 128);       // (8, 32)
    gemm_ps<<<ggrid, 256, GEMM_SMEM>>>(xh + 0 * NX, xl + 0 * NX, wh + 0 * NW, wl + 0 * NW,
                                       bq, nullptr, Qh, Ql, 1);
    gemm_ps<<<ggrid, 256, GEMM_SMEM>>>(xh + 1 * NX, xl + 1 * NX, wh + 1 * NW, wl + 1 * NW,
                                       bk, nullptr, Kh, Kl, 1);
    gemm_ps<<<ggrid, 256, GEMM_SMEM>>>(xh + 2 * NX, xl + 2 * NX, wh + 2 * NW, wl + 2 * NW,
                                       bv, nullptr, Vh, Vl, 1);

    dim3 agrid(SEQ / 128, BH);              // (16, 32)
    attn_mma<<<agrid, 256, ATT_SMEM>>>(Qh, Ql, Kh, Kl, Vh, Vl, pM, Ah, Al);

    gemm_ps<<<ggrid, 256, GEMM_SMEM>>>(Ah, Al, wh + 3 * NW, wl + 3 * NW,
                                       bo, (float*)d_out, nullptr, nullptr, 0);
}

// round 14
// speedup vs baseline: 1.0731x; 1.0651x over previous
#include <cuda_runtime.h>
#include <cuda_bf16.h>
#include <math.h>
#include <stdint.h>

// Problem constants (fixed by setup_inputs)
#define BATCH   2
#define SEQ     2048
#define DM      1024
#define NH      16
#define HD      64
#define MTOT    (BATCH * SEQ)      // 4096
#define BH      (BATCH * NH)       // 32

typedef __nv_bfloat16 bf16;

// ---------------- scratch (static device globals; no allocs allowed) -------
__device__ bf16 g_xh[3][(size_t)MTOT * DM];      // split inputs q,k,v
__device__ bf16 g_xl[3][(size_t)MTOT * DM];
__device__ bf16 g_wh[4][(size_t)DM * DM];        // split weights Wq,Wk,Wv,Wo
__device__ bf16 g_wl[4][(size_t)DM * DM];
__device__ bf16 g_Qh[(size_t)BH * SEQ * HD], g_Ql[(size_t)BH * SEQ * HD];
__device__ bf16 g_Kh[(size_t)BH * SEQ * HD], g_Kl[(size_t)BH * SEQ * HD];
__device__ bf16 g_Vh[(size_t)BH * SEQ * HD], g_Vl[(size_t)BH * SEQ * HD];
__device__ bf16 g_Ah[(size_t)MTOT * DM], g_Al[(size_t)MTOT * DM];  // attn out
__device__ float g_maskbias[MTOT];               // [b][l] -> 0 or -inf

// ======================= helpers ==========================================
__device__ __forceinline__ uint32_t smem_u32(const void* p) {
    uint32_t a;
    asm("{ .reg .u64 t; cvta.to.shared.u64 t, %1; cvt.u32.u64 %0, t; }"
        : "=r"(a) : "l"(p));
    return a;
}

// split fp32 -> (hi, lo) bf16x2 pairs
__device__ __forceinline__ void cvt2_split(float a, float b, uint32_t& h, uint32_t& l) {
    __nv_bfloat162 hh = __floats2bfloat162_rn(a, b);
    float ra = a - __bfloat162float(__low2bfloat16(hh));
    float rb = b - __bfloat162float(__high2bfloat16(hh));
    __nv_bfloat162 ll = __floats2bfloat162_rn(ra, rb);
    h = *reinterpret_cast<uint32_t*>(&hh);
    l = *reinterpret_cast<uint32_t*>(&ll);
}

#define LDMX4(r0, r1, r2, r3, addr)                                           \
    asm volatile("ldmatrix.sync.aligned.m8n8.x4.shared.b16 {%0,%1,%2,%3}, [%4];" \
        : "=r"(r0), "=r"(r1), "=r"(r2), "=r"(r3) : "r"(addr))

#define LDMX4T(r0, r1, r2, r3, addr)                                          \
    asm volatile("ldmatrix.sync.aligned.m8n8.x4.trans.shared.b16 {%0,%1,%2,%3}, [%4];" \
        : "=r"(r0), "=r"(r1), "=r"(r2), "=r"(r3) : "r"(addr))

#define MMA16816(c, a, b)                                                     \
    asm volatile("mma.sync.aligned.m16n8k16.row.col.f32.bf16.bf16.f32 "       \
        "{%0,%1,%2,%3}, {%4,%5,%6,%7}, {%8,%9}, {%0,%1,%2,%3};"               \
        : "+f"((c)[0]), "+f"((c)[1]), "+f"((c)[2]), "+f"((c)[3])              \
        : "r"((a)[0]), "r"((a)[1]), "r"((a)[2]), "r"((a)[3]),                 \
          "r"((b)[0]), "r"((b)[1]))

#define CPA16(dst, src)                                                       \
    asm volatile("cp.async.cg.shared.global [%0], [%1], 16;"                  \
        :: "r"(dst), "l"(src))
#define CPA_COMMIT() asm volatile("cp.async.commit_group;" ::: "memory")
#define CPA_WAIT1()  asm volatile("cp.async.wait_group 1;" ::: "memory")
#define CPA_WAIT0()  asm volatile("cp.async.wait_group 0;" ::: "memory")

// ================== mask dtype sniff + convert to float bias ===============
__global__ __launch_bounds__(1024) void mask_convert(const void* __restrict__ mask)
{
    __shared__ int s_f32, s_u8;
    const unsigned int* w = (const unsigned int*)mask;
    const int tid = threadIdx.x;
    if (tid == 0) { s_f32 = 0; s_u8 = 0; }
    __syncthreads();
    unsigned int x = w[tid];
    if (x == 0x3F800000u) atomicOr(&s_f32, 1);
    else if (x > 1u)      atomicOr(&s_u8, 1);
    __syncthreads();
    const int cls = s_f32 ? 2 : (s_u8 ? 0 : 1);

#pragma unroll
    for (int u = 0; u < 4; u++) {
        int i = tid * 4 + u;
        bool m;
        if (cls == 0)      m = ((const unsigned char*)mask)[i] != 0;
        else if (cls == 1) m = ((const int*)mask)[i] != 0;
        else               m = ((const unsigned int*)mask)[i] != 0u;
        g_maskbias[i] = m ? -INFINITY : 0.f;
    }
}

// ================== fp32 -> split bf16 hi/lo (elementwise) =================
__global__ __launch_bounds__(256) void cvt_split_kernel(
    const float* __restrict__ src, bf16* __restrict__ dh,
    bf16* __restrict__ dl, int n4)
{
    int i = blockIdx.x * blockDim.x + threadIdx.x;
    if (i >= n4) return;
    float4 u = ((const float4*)src)[i];
    uint2 h, l;
    cvt2_split(u.x, u.y, h.x, l.x);
    cvt2_split(u.z, u.w, h.y, l.y);
    ((uint2*)dh)[i] = h;
    ((uint2*)dl)[i] = l;
}

// ===== pipelined split-bf16 GEMM: C = A*B^T + bias (CTA 128x256, BK=64) ====
// 8 warps, warp tile 64x64. 2-stage cp.async. XOR-swizzled smem (no pad).
// Stage layout: Ahi[128x64] Alo[128x64] Bhi[256x64] Blo[256x64], rows = 128 B.
#define AHB   16384                  // bytes per A buffer (128 rows x 128 B)
#define BHB   32768                  // bytes per B buffer (256 rows x 128 B)
#define STG   (2 * AHB + 2 * BHB)    // 98304 per stage
#define GSMEM (2 * STG)              // 196608

__global__ __launch_bounds__(256, 1) void gemm_ps(
    const bf16* __restrict__ Ah, const bf16* __restrict__ Al,
    const bf16* __restrict__ Bh, const bf16* __restrict__ Bl,
    const float* __restrict__ bias, float* __restrict__ Cf,
    bf16* __restrict__ Ch, bf16* __restrict__ Cl, int permute)
{
    extern __shared__ char smem[];
    const uint32_t sb = smem_u32(smem);
    const int tid  = threadIdx.x;
    const int wid  = tid >> 5;
    const int lane = tid & 31;
    const int bm = blockIdx.y * 128;
    const int bn = blockIdx.x * 256;
    const int wm = (wid & 1) * 64;           // warp m-offset
    const int wn = (wid >> 1) * 64;          // warp n-offset (4 groups of 64)

    const int lr  = lane & 7;
    const int l8  = (lane >> 3) & 1;
    const int l16 = (lane >> 4) & 1;

    // issue cp.async for one stage (6144 x 16B chunks, 24 per thread)
    auto issue = [&](int stage, int k0) {
#pragma unroll
        for (int i = 0; i < 24; i++) {
            int c = tid + i * 256;           // 0..6143
            int seg = c & 7;
            const bf16* src;
            uint32_t dst;
            if (c < 2048) {                  // A region (i < 8)
                int buf = c >> 10;           // 0=hi 1=lo
                int r   = (c >> 3) & 127;
                src = (buf ? Al : Ah) + (size_t)(bm + r) * DM + k0 + seg * 8;
                dst = sb + stage * STG + buf * AHB
                    + r * 128 + (((seg ^ (r & 7))) << 4);
            } else {                         // B region
                int c2  = c - 2048;
                int buf = c2 >> 11;          // 0=hi 1=lo
                int r   = (c2 >> 3) & 255;
                src = (buf ? Bl : Bh) + (size_t)(bn + r) * DM + k0 + seg * 8;
                dst = sb + stage * STG + 2 * AHB + buf * BHB
                    + r * 128 + (((seg ^ (r & 7))) << 4);
            }
            CPA16(dst, src);
        }
        CPA_COMMIT();
    };

    float acc[4][8][4];
#pragma unroll
    for (int i = 0; i < 4; i++)
#pragma unroll
        for (int j = 0; j < 8; j++)
#pragma unroll
            for (int c = 0; c < 4; c++) acc[i][j][c] = 0.f;

    issue(0, 0);

    const int NCH = DM / 64;                 // 16
    for (int ch = 0; ch < NCH; ch++) {
        if (ch + 1 < NCH) { issue((ch + 1) & 1, (ch + 1) * 64); CPA_WAIT1(); }
        else              { CPA_WAIT0(); }
        __syncthreads();
        const uint32_t st = sb + (ch & 1) * STG;

#pragma unroll
        for (int ks = 0; ks < 4; ks++) {
            uint32_t aH[4][4], aL[4][4];
#pragma unroll
            for (int mt = 0; mt < 4; mt++) {
                int row = wm + mt * 16 + lr + l8 * 8;
                uint32_t off = (uint32_t)row * 128
                             + (uint32_t)(((ks * 2 + l16) ^ (row & 7)) << 4);
                LDMX4(aH[mt][0], aH[mt][1], aH[mt][2], aH[mt][3], st + off);
                LDMX4(aL[mt][0], aL[mt][1], aL[mt][2], aL[mt][3], st + AHB + off);
            }
            uint32_t bH[8][2], bL[8][2];
#pragma unroll
            for (int np = 0; np < 4; np++) {
                int row = wn + np * 16 + lr + l16 * 8;
                uint32_t off = (uint32_t)row * 128
                             + (uint32_t)(((ks * 2 + l8) ^ (row & 7)) << 4);
                uint32_t r0, r1, r2, r3;
                LDMX4(r0, r1, r2, r3, st + 2 * AHB + off);
                bH[np * 2][0] = r0; bH[np * 2][1] = r1;
                bH[np * 2 + 1][0] = r2; bH[np * 2 + 1][1] = r3;
                LDMX4(r0, r1, r2, r3, st + 2 * AHB + BHB + off);
                bL[np * 2][0] = r0; bL[np * 2][1] = r1;
                bL[np * 2 + 1][0] = r2; bL[np * 2 + 1][1] = r3;
            }
#pragma unroll
            for (int mt = 0; mt < 4; mt++)
#pragma unroll
                for (int nt = 0; nt < 8; nt++) {
                    MMA16816(acc[mt][nt], aH[mt], bH[nt]);
                    MMA16816(acc[mt][nt], aH[mt], bL[nt]);
                    MMA16816(acc[mt][nt], aL[mt], bH[nt]);
                }
        }
        __syncthreads();                     // readers done before overwrite
    }

    // ---- epilogue ----
    const int crow = lane >> 2;
    const int ccol = (lane & 3) * 2;
#pragma unroll
    for (int mt = 0; mt < 4; mt++) {
#pragma unroll
        for (int nt = 0; nt < 8; nt++) {
            int n0 = bn + wn + nt * 8 + ccol;
            float b0 = bias[n0], b1 = bias[n0 + 1];
#pragma unroll
            for (int half = 0; half < 2; half++) {
                int m = bm + wm + mt * 16 + crow + half * 8;
                float v0 = acc[mt][nt][half * 2 + 0] + b0;
                float v1 = acc[mt][nt][half * 2 + 1] + b1;
                if (!permute) {
                    float2 v; v.x = v0; v.y = v1;
                    *(float2*)(Cf + (size_t)m * DM + n0) = v;
                } else {
                    int b_ = m >> 11;
                    int l  = m & (SEQ - 1);
                    int h  = n0 >> 6;
                    int d  = n0 & (HD - 1);
                    size_t idx = ((size_t)(b_ * NH + h) * SEQ + l) * HD + d;
                    uint32_t hh, ll;
                    cvt2_split(v0, v1, hh, ll);
                    *(uint32_t*)(Ch + idx) = hh;
                    *(uint32_t*)(Cl + idx) = ll;
                }
            }
        }
    }
}

// ============== Flash attention on mma.sync (pre-split bf16) ===============
// BM=128 q-rows/CTA (8 warps x 16 rows), BN=64 kv per tile.
#define APAD  72
#define AQTI  (128 * APAD * 2)     // 18432 B (Q buffers: 128 rows)
#define AKTI  (64 * APAD * 2)      // 9216 B  (K/V buffers: 64 rows)
#define A_QH  0
#define A_QL  (AQTI)
#define A_KH  (2 * AQTI)
#define A_KL  (2 * AQTI + AKTI)
#define A_VH  (2 * AQTI + 2 * AKTI)
#define A_VL  (2 * AQTI + 3 * AKTI)
#define A_MS  (2 * AQTI + 4 * AKTI)
#define ATT_SMEM (A_MS + 256)      // 74 KB

__global__ __launch_bounds__(256) void attn_mma(
    const bf16* __restrict__ Qh, const bf16* __restrict__ Ql,
    const bf16* __restrict__ Kh, const bf16* __restrict__ Kl,
    const bf16* __restrict__ Vh, const bf16* __restrict__ Vl,
    const float* __restrict__ maskbias,
    bf16* __restrict__ Oh, bf16* __restrict__ Ol)
{
    extern __shared__ char smem[];
    const uint32_t sb = smem_u32(smem);
    float* Ms = (float*)(smem + A_MS);

    const int bh = blockIdx.y;
    const int b_ = bh >> 4;
    const int h  = bh & (NH - 1);
    const int q0 = blockIdx.x * 128;
    const int tid  = threadIdx.x;
    const int wid  = tid >> 5;               // 0..7 -> q-rows [wid*16, wid*16+16)
    const int lane = tid & 31;
    const int lr  = lane & 7;
    const int l8  = (lane >> 3) & 1;
    const int l16 = (lane >> 4) & 1;
    const int crow = lane >> 2;
    const int ccol = (lane & 3) * 2;
    const float scale = 0.125f;              // 1/sqrt(64)

    // ---- copy Q tile (128x64 bf16, hi+lo) ----
    {
        const bf16* srcs[2] = {Qh + ((size_t)bh * SEQ + q0) * HD,
                               Ql + ((size_t)bh * SEQ + q0) * HD};
        const uint32_t doff[2] = {A_QH, A_QL};
#pragma unroll
        for (int i = 0; i < 8; i++) {
            int c = tid + i * 256;           // 0..2047
            int buf = c >> 10;
            int r   = (c >> 3) & 127;
            int seg = c & 7;
            uint4 v = *(const uint4*)(srcs[buf] + r * HD + seg * 8);
            *(uint4*)(smem + doff[buf] + r * APAD * 2 + seg * 16) = v;
        }
    }

    float O[8][4];
#pragma unroll
    for (int i = 0; i < 8; i++)
#pragma unroll
        for (int j = 0; j < 4; j++) O[i][j] = 0.f;
    float m0 = -INFINITY, m1 = -INFINITY, li0 = 0.f, li1 = 0.f;
    __syncthreads();

    for (int t = 0; t < SEQ / 64; t++) {
        const int k0 = t * 64;
        {
            const bf16* srcs[4] = {Kh + ((size_t)bh * SEQ + k0) * HD,
                                   Kl + ((size_t)bh * SEQ + k0) * HD,
                                   Vh + ((size_t)bh * SEQ + k0) * HD,
                                   Vl + ((size_t)bh * SEQ + k0) * HD};
            const uint32_t doff[4] = {A_KH, A_KL, A_VH, A_VL};
#pragma unroll
            for (int i = 0; i < 8; i++) {
                int c = tid + i * 256;       // 0..2047
                int buf = c >> 9;
                int r   = (c >> 3) & 63;
                int seg = c & 7;
                uint4 v = *(const uint4*)(srcs[buf] + r * HD + seg * 8);
                *(uint4*)(smem + doff[buf] + r * APAD * 2 + seg * 16) = v;
            }
        }
        if (tid < 64) Ms[tid] = maskbias[(size_t)b_ * SEQ + k0 + tid];
        __syncthreads();

        // ---- S = Q * K^T (warp: 16 q-rows x 64 kv) ----
        float S[8][4];
#pragma unroll
        for (int i = 0; i < 8; i++)
#pragma unroll
            for (int j = 0; j < 4; j++) S[i][j] = 0.f;

#pragma unroll
        for (int ks = 0; ks < 4; ks++) {
            uint32_t aH[4], aL[4];
            uint32_t offa = (uint32_t)((wid * 16 + lr + l8 * 8) * APAD
                                       + ks * 16 + l16 * 8) * 2;
            LDMX4(aH[0], aH[1], aH[2], aH[3], sb + A_QH + offa);
            LDMX4(aL[0], aL[1], aL[2], aL[3], sb + A_QL + offa);
            uint32_t bH[8][2], bL[8][2];
#pragma unroll
            for (int np = 0; np < 4; np++) {
                uint32_t offb = (uint32_t)((np * 16 + lr + l16 * 8) * APAD
                                           + ks * 16 + l8 * 8) * 2;
                uint32_t r0, r1, r2, r3;
                LDMX4(r0, r1, r2, r3, sb + A_KH + offb);
                bH[np * 2][0] = r0; bH[np * 2][1] = r1;
                bH[np * 2 + 1][0] = r2; bH[np * 2 + 1][1] = r3;
                LDMX4(r0, r1, r2, r3, sb + A_KL + offb);
                bL[np * 2][0] = r0; bL[np * 2][1] = r1;
                bL[np * 2 + 1][0] = r2; bL[np * 2 + 1][1] = r3;
            }
#pragma unroll
            for (int nt = 0; nt < 8; nt++) {
                MMA16816(S[nt], aH, bH[nt]);
                MMA16816(S[nt], aH, bL[nt]);
                MMA16816(S[nt], aL, bH[nt]);
            }
        }

        // ---- softmax ----
        float rm0 = -INFINITY, rm1 = -INFINITY;
#pragma unroll
        for (int nt = 0; nt < 8; nt++) {
            float mk0 = Ms[nt * 8 + ccol], mk1 = Ms[nt * 8 + ccol + 1];
            S[nt][0] = S[nt][0] * scale + mk0;
            S[nt][1] = S[nt][1] * scale + mk1;
            S[nt][2] = S[nt][2] * scale + mk0;
            S[nt][3] = S[nt][3] * scale + mk1;
            rm0 = fmaxf(rm0, fmaxf(S[nt][0], S[nt][1]));
            rm1 = fmaxf(rm1, fmaxf(S[nt][2], S[nt][3]));
        }
        rm0 = fmaxf(rm0, __shfl_xor_sync(0xffffffffu, rm0, 1));
        rm0 = fmaxf(rm0, __shfl_xor_sync(0xffffffffu, rm0, 2));
        rm1 = fmaxf(rm1, __shfl_xor_sync(0xffffffffu, rm1, 1));
        rm1 = fmaxf(rm1, __shfl_xor_sync(0xffffffffu, rm1, 2));

        float mn0 = fmaxf(m0, rm0), mn1 = fmaxf(m1, rm1);
        float ms0 = fmaxf(mn0, -1e30f), ms1 = fmaxf(mn1, -1e30f);
        float al0 = __expf(m0 - ms0), al1 = __expf(m1 - ms1);
        m0 = mn0; m1 = mn1;

        float rs0 = 0.f, rs1 = 0.f;
        uint32_t pH[4][4], pL[4][4];
#pragma unroll
        for (int nt = 0; nt < 8; nt++) {
            float p0 = __expf(S[nt][0] - ms0);
            float p1 = __expf(S[nt][1] - ms0);
            float p2 = __expf(S[nt][2] - ms1);
            float p3 = __expf(S[nt][3] - ms1);
            rs0 += p0 + p1; rs1 += p2 + p3;
            int ks2 = nt >> 1, base = (nt & 1) * 2;
            uint32_t h01, l01, h23, l23;
            cvt2_split(p0, p1, h01, l01);
            cvt2_split(p2, p3, h23, l23);
            pH[ks2][base] = h01; pH[ks2][base + 1] = h23;
            pL[ks2][base] = l01; pL[ks2][base + 1] = l23;
        }
        rs0 += __shfl_xor_sync(0xffffffffu, rs0, 1);
        rs0 += __shfl_xor_sync(0xffffffffu, rs0, 2);
        rs1 += __shfl_xor_sync(0xffffffffu, rs1, 1);
        rs1 += __shfl_xor_sync(0xffffffffu, rs1, 2);
        li0 = li0 * al0 + rs0;
        li1 = li1 * al1 + rs1;
#pragma unroll
        for (int nt = 0; nt < 8; nt++) {
            O[nt][0] *= al0; O[nt][1] *= al0;
            O[nt][2] *= al1; O[nt][3] *= al1;
        }

        // ---- O += P * V ----
#pragma unroll
        for (int ks2 = 0; ks2 < 4; ks2++) {
            uint32_t bH2[8][2], bL2[8][2];
#pragma unroll
            for (int np = 0; np < 4; np++) {
                uint32_t offv = (uint32_t)((ks2 * 16 + lr + l8 * 8) * APAD
                                           + np * 16 + l16 * 8) * 2;
                uint32_t r0, r1, r2, r3;
                LDMX4T(r0, r1, r2, r3, sb + A_VH + offv);
                bH2[np * 2][0] = r0; bH2[np * 2][1] = r1;
                bH2[np * 2 + 1][0] = r2; bH2[np * 2 + 1][1] = r3;
                LDMX4T(r0, r1, r2, r3, sb + A_VL + offv);
                bL2[np * 2][0] = r0; bL2[np * 2][1] = r1;
                bL2[np * 2 + 1][0] = r2; bL2[np * 2 + 1][1] = r3;
            }
#pragma unroll
            for (int nt = 0; nt < 8; nt++) {
                MMA16816(O[nt], pH[ks2], bH2[nt]);
                MMA16816(O[nt], pH[ks2], bL2[nt]);
                MMA16816(O[nt], pL[ks2], bH2[nt]);
            }
        }
        __syncthreads();
    }

    // ---- normalize + split-write out[b][l][h*64 + d] ----
    float inv0 = 1.f / li0, inv1 = 1.f / li1;
    int l0 = q0 + wid * 16 + crow;
    size_t base0 = ((size_t)b_ * SEQ + l0) * DM + h * HD;
    size_t base1 = base0 + (size_t)8 * DM;
#pragma unroll
    for (int nt = 0; nt < 8; nt++) {
        int col = nt * 8 + ccol;
        uint32_t hh, ll;
        cvt2_split(O[nt][0] * inv0, O[nt][1] * inv0, hh, ll);
        *(uint32_t*)(Oh + base0 + col) = hh;
        *(uint32_t*)(Ol + base0 + col) = ll;
        cvt2_split(O[nt][2] * inv1, O[nt][3] * inv1, hh, ll);
        *(uint32_t*)(Oh + base1 + col) = hh;
        *(uint32_t*)(Ol + base1 + col) = ll;
    }
}

// ================================ launch ===================================
extern "C" void kernel_launch(void* const* d_in, const int* in_sizes, int n_in,
                              void* d_out, int out_size)
{
    const float* q    = (const float*)d_in[0];
    const float* k    = (const float*)d_in[1];
    const float* v    = (const float*)d_in[2];
    const void*  mask = (const void*)d_in[3];
    const float* Wq = (const float*)d_in[4];
    const float* bq = (const float*)d_in[5];
    const float* Wk = (const float*)d_in[6];
    const float* bk = (const float*)d_in[7];
    const float* Wv = (const float*)d_in[8];
    const float* bv = (const float*)d_in[9];
    const float* Wo = (const float*)d_in[10];
    const float* bo = (const float*)d_in[11];

    bf16 *xh, *xl, *wh, *wl;
    bf16 *Qh, *Ql, *Kh, *Kl, *Vh, *Vl, *Ah, *Al;
    float* pM;
    cudaGetSymbolAddress((void**)&xh, g_xh);
    cudaGetSymbolAddress((void**)&xl, g_xl);
    cudaGetSymbolAddress((void**)&wh, g_wh);
    cudaGetSymbolAddress((void**)&wl, g_wl);
    cudaGetSymbolAddress((void**)&Qh, g_Qh);
    cudaGetSymbolAddress((void**)&Ql, g_Ql);
    cudaGetSymbolAddress((void**)&Kh, g_Kh);
    cudaGetSymbolAddress((void**)&Kl, g_Kl);
    cudaGetSymbolAddress((void**)&Vh, g_Vh);
    cudaGetSymbolAddress((void**)&Vl, g_Vl);
    cudaGetSymbolAddress((void**)&Ah, g_Ah);
    cudaGetSymbolAddress((void**)&Al, g_Al);
    cudaGetSymbolAddress((void**)&pM, g_maskbias);

    cudaFuncSetAttribute(gemm_ps, cudaFuncAttributeMaxDynamicSharedMemorySize,
                         GSMEM);
    cudaFuncSetAttribute(attn_mma, cudaFuncAttributeMaxDynamicSharedMemorySize,
                         ATT_SMEM);

    mask_convert<<<1, 1024>>>(mask);

    // pre-split all fp32 operands into bf16 hi/lo
    const size_t NX = (size_t)MTOT * DM;     // 4M
    const size_t NW = (size_t)DM * DM;       // 1M
    cvt_split_kernel<<<(int)(NX / 4 / 256), 256>>>(q,  xh + 0 * NX, xl + 0 * NX, (int)(NX / 4));
    cvt_split_kernel<<<(int)(NX / 4 / 256), 256>>>(k,  xh + 1 * NX, xl + 1 * NX, (int)(NX / 4));
    cvt_split_kernel<<<(int)(NX / 4 / 256), 256>>>(v,  xh + 2 * NX, xl + 2 * NX, (int)(NX / 4));
    cvt_split_kernel<<<(int)(NW / 4 / 256), 256>>>(Wq, wh + 0 * NW, wl + 0 * NW, (int)(NW / 4));
    cvt_split_kernel<<<(int)(NW / 4 / 256), 256>>>(Wk, wh + 1 * NW, wl + 1 * NW, (int)(NW / 4));
    cvt_split_kernel<<<(int)(NW / 4 / 256), 256>>>(Wv, wh + 2 * NW, wl + 2 * NW, (int)(NW / 4));
    cvt_split_kernel<<<(int)(NW / 4 / 256), 256>>>(Wo, wh + 3 * NW, wl + 3 * NW, (int)(NW / 4));

    dim3 ggrid(DM / 256, MTOT / 128);       // (4, 32) = 128 CTAs = 1 wave
    gemm_ps<<<ggrid, 256, GSMEM>>>(xh + 0 * NX, xl + 0 * NX, wh + 0 * NW, wl + 0 * NW,
                                   bq, nullptr, Qh, Ql, 1);
    gemm_ps<<<ggrid, 256, GSMEM>>>(xh + 1 * NX, xl + 1 * NX, wh + 1 * NW, wl + 1 * NW,
                                   bk, nullptr, Kh, Kl, 1);
    gemm_ps<<<ggrid, 256, GSMEM>>>(xh + 2 * NX, xl + 2 * NX, wh + 2 * NW, wl + 2 * NW,
                                   bv, nullptr, Vh, Vl, 1);

    dim3 agrid(SEQ / 128, BH);              // (16, 32)
    attn_mma<<<agrid, 256, ATT_SMEM>>>(Qh, Ql, Kh, Kl, Vh, Vl, pM, Ah, Al);

    gemm_ps<<<ggrid, 256, GSMEM>>>(Ah, Al, wh + 3 * NW, wl + 3 * NW,
                                   bo, (float*)d_out, nullptr, nullptr, 0);
}

// round 15
// speedup vs baseline: 1.1346x; 1.0573x over previous
#include <cuda_runtime.h>
#include <cuda_bf16.h>
#include <math.h>
#include <stdint.h>

// Problem constants (fixed by setup_inputs)
#define BATCH   2
#define SEQ     2048
#define DM      1024
#define NH      16
#define HD      64
#define MTOT    (BATCH * SEQ)      // 4096
#define BH      (BATCH * NH)       // 32

typedef __nv_bfloat16 bf16;

// ---------------- scratch (static device globals; no allocs allowed) -------
__device__ bf16 g_xh[3][(size_t)MTOT * DM];      // split inputs q,k,v
__device__ bf16 g_xl[3][(size_t)MTOT * DM];
__device__ bf16 g_wh[4][(size_t)DM * DM];        // split weights Wq,Wk,Wv,Wo
__device__ bf16 g_wl[4][(size_t)DM * DM];
__device__ bf16 g_Qh[(size_t)BH * SEQ * HD], g_Ql[(size_t)BH * SEQ * HD];
__device__ bf16 g_Kh[(size_t)BH * SEQ * HD], g_Kl[(size_t)BH * SEQ * HD];
__device__ bf16 g_Vh[(size_t)BH * SEQ * HD], g_Vl[(size_t)BH * SEQ * HD];
__device__ bf16 g_Ah[(size_t)MTOT * DM], g_Al[(size_t)MTOT * DM];  // attn out
__device__ float g_maskbias[MTOT];               // [b][l] -> 0 or -inf

// ======================= helpers ==========================================
__device__ __forceinline__ uint32_t smem_u32(const void* p) {
    uint32_t a;
    asm("{ .reg .u64 t; cvta.to.shared.u64 t, %1; cvt.u32.u64 %0, t; }"
        : "=r"(a) : "l"(p));
    return a;
}

// split fp32 -> (hi, lo) bf16x2 pairs
__device__ __forceinline__ void cvt2_split(float a, float b, uint32_t& h, uint32_t& l) {
    __nv_bfloat162 hh = __floats2bfloat162_rn(a, b);
    float ra = a - __bfloat162float(__low2bfloat16(hh));
    float rb = b - __bfloat162float(__high2bfloat16(hh));
    __nv_bfloat162 ll = __floats2bfloat162_rn(ra, rb);
    h = *reinterpret_cast<uint32_t*>(&hh);
    l = *reinterpret_cast<uint32_t*>(&ll);
}

#define LDMX4(r0, r1, r2, r3, addr)                                           \
    asm volatile("ldmatrix.sync.aligned.m8n8.x4.shared.b16 {%0,%1,%2,%3}, [%4];" \
        : "=r"(r0), "=r"(r1), "=r"(r2), "=r"(r3) : "r"(addr))

#define LDMX4T(r0, r1, r2, r3, addr)                                          \
    asm volatile("ldmatrix.sync.aligned.m8n8.x4.trans.shared.b16 {%0,%1,%2,%3}, [%4];" \
        : "=r"(r0), "=r"(r1), "=r"(r2), "=r"(r3) : "r"(addr))

#define MMA16816(c, a, b)                                                     \
    asm volatile("mma.sync.aligned.m16n8k16.row.col.f32.bf16.bf16.f32 "       \
        "{%0,%1,%2,%3}, {%4,%5,%6,%7}, {%8,%9}, {%0,%1,%2,%3};"               \
        : "+f"((c)[0]), "+f"((c)[1]), "+f"((c)[2]), "+f"((c)[3])              \
        : "r"((a)[0]), "r"((a)[1]), "r"((a)[2]), "r"((a)[3]),                 \
          "r"((b)[0]), "r"((b)[1]))

#define CPA16(dst, src)                                                       \
    asm volatile("cp.async.cg.shared.global [%0], [%1], 16;"                  \
        :: "r"(dst), "l"(src))
#define CPA_COMMIT() asm volatile("cp.async.commit_group;" ::: "memory")
#define CPA_WAIT1()  asm volatile("cp.async.wait_group 1;" ::: "memory")
#define CPA_WAIT0()  asm volatile("cp.async.wait_group 0;" ::: "memory")

// ================== mask dtype sniff + convert to float bias ===============
__global__ __launch_bounds__(1024) void mask_convert(const void* __restrict__ mask)
{
    __shared__ int s_f32, s_u8;
    const unsigned int* w = (const unsigned int*)mask;
    const int tid = threadIdx.x;
    if (tid == 0) { s_f32 = 0; s_u8 = 0; }
    __syncthreads();
    unsigned int x = w[tid];
    if (x == 0x3F800000u) atomicOr(&s_f32, 1);
    else if (x > 1u)      atomicOr(&s_u8, 1);
    __syncthreads();
    const int cls = s_f32 ? 2 : (s_u8 ? 0 : 1);

#pragma unroll
    for (int u = 0; u < 4; u++) {
        int i = tid * 4 + u;
        bool m;
        if (cls == 0)      m = ((const unsigned char*)mask)[i] != 0;
        else if (cls == 1) m = ((const int*)mask)[i] != 0;
        else               m = ((const unsigned int*)mask)[i] != 0u;
        g_maskbias[i] = m ? -INFINITY : 0.f;
    }
}

// ============== fp32 -> split bf16 hi/lo, ALL tensors, one launch ==========
struct CvtJobs {
    const float* src[7];
    bf16* dh[7];
    bf16* dl[7];
};
// jobs 0-2: 1M float4 each (inputs); jobs 3-6: 256K float4 each (weights)
#define CVT_IN4   1048576
#define CVT_W4    262144
#define CVT_TOT4  (3 * CVT_IN4 + 4 * CVT_W4)   // 4,194,304

__global__ __launch_bounds__(256) void cvt_all(CvtJobs jobs)
{
    int i = blockIdx.x * 256 + threadIdx.x;
    if (i >= CVT_TOT4) return;
    int job, off;
    if (i < 3 * CVT_IN4) { job = i >> 20;  off = i & (CVT_IN4 - 1); }
    else { int j = i - 3 * CVT_IN4; job = 3 + (j >> 18); off = j & (CVT_W4 - 1); }
    float4 u = ((const float4*)jobs.src[job])[off];
    uint2 h, l;
    cvt2_split(u.x, u.y, h.x, l.x);
    cvt2_split(u.z, u.w, h.y, l.y);
    ((uint2*)jobs.dh[job])[off] = h;
    ((uint2*)jobs.dl[job])[off] = l;
}

// ===== pipelined split-bf16 GEMM: C = A*B^T + bias (CTA 128x256, BK=64) ====
// 8 warps, warp tile 64x64. 2-stage cp.async. XOR-swizzled smem (no pad).
#define AHB   16384                  // bytes per A buffer (128 rows x 128 B)
#define BHB   32768                  // bytes per B buffer (256 rows x 128 B)
#define STG   (2 * AHB + 2 * BHB)    // 98304 per stage
#define GSMEM (2 * STG)              // 196608

__global__ __launch_bounds__(256, 1) void gemm_ps(
    const bf16* __restrict__ Ah, const bf16* __restrict__ Al,
    const bf16* __restrict__ Bh, const bf16* __restrict__ Bl,
    const float* __restrict__ bias, float* __restrict__ Cf,
    bf16* __restrict__ Ch, bf16* __restrict__ Cl, int permute)
{
    extern __shared__ char smem[];
    const uint32_t sb = smem_u32(smem);
    const int tid  = threadIdx.x;
    const int wid  = tid >> 5;
    const int lane = tid & 31;
    const int bm = blockIdx.y * 128;
    const int bn = blockIdx.x * 256;
    const int wm = (wid & 1) * 64;
    const int wn = (wid >> 1) * 64;

    const int lr  = lane & 7;
    const int l8  = (lane >> 3) & 1;
    const int l16 = (lane >> 4) & 1;

    auto issue = [&](int stage, int k0) {
#pragma unroll
        for (int i = 0; i < 24; i++) {
            int c = tid + i * 256;           // 0..6143
            int seg = c & 7;
            const bf16* src;
            uint32_t dst;
            if (c < 2048) {
                int buf = c >> 10;
                int r   = (c >> 3) & 127;
                src = (buf ? Al : Ah) + (size_t)(bm + r) * DM + k0 + seg * 8;
                dst = sb + stage * STG + buf * AHB
                    + r * 128 + (((seg ^ (r & 7))) << 4);
            } else {
                int c2  = c - 2048;
                int buf = c2 >> 11;
                int r   = (c2 >> 3) & 255;
                src = (buf ? Bl : Bh) + (size_t)(bn + r) * DM + k0 + seg * 8;
                dst = sb + stage * STG + 2 * AHB + buf * BHB
                    + r * 128 + (((seg ^ (r & 7))) << 4);
            }
            CPA16(dst, src);
        }
        CPA_COMMIT();
    };

    float acc[4][8][4];
#pragma unroll
    for (int i = 0; i < 4; i++)
#pragma unroll
        for (int j = 0; j < 8; j++)
#pragma unroll
            for (int c = 0; c < 4; c++) acc[i][j][c] = 0.f;

    issue(0, 0);

    const int NCH = DM / 64;                 // 16
    for (int ch = 0; ch < NCH; ch++) {
        if (ch + 1 < NCH) { issue((ch + 1) & 1, (ch + 1) * 64); CPA_WAIT1(); }
        else              { CPA_WAIT0(); }
        __syncthreads();
        const uint32_t st = sb + (ch & 1) * STG;

#pragma unroll
        for (int ks = 0; ks < 4; ks++) {
            uint32_t aH[4][4], aL[4][4];
#pragma unroll
            for (int mt = 0; mt < 4; mt++) {
                int row = wm + mt * 16 + lr + l8 * 8;
                uint32_t off = (uint32_t)row * 128
                             + (uint32_t)(((ks * 2 + l16) ^ (row & 7)) << 4);
                LDMX4(aH[mt][0], aH[mt][1], aH[mt][2], aH[mt][3], st + off);
                LDMX4(aL[mt][0], aL[mt][1], aL[mt][2], aL[mt][3], st + AHB + off);
            }
            uint32_t bH[8][2], bL[8][2];
#pragma unroll
            for (int np = 0; np < 4; np++) {
                int row = wn + np * 16 + lr + l16 * 8;
                uint32_t off = (uint32_t)row * 128
                             + (uint32_t)(((ks * 2 + l8) ^ (row & 7)) << 4);
                uint32_t r0, r1, r2, r3;
                LDMX4(r0, r1, r2, r3, st + 2 * AHB + off);
                bH[np * 2][0] = r0; bH[np * 2][1] = r1;
                bH[np * 2 + 1][0] = r2; bH[np * 2 + 1][1] = r3;
                LDMX4(r0, r1, r2, r3, st + 2 * AHB + BHB + off);
                bL[np * 2][0] = r0; bL[np * 2][1] = r1;
                bL[np * 2 + 1][0] = r2; bL[np * 2 + 1][1] = r3;
            }
#pragma unroll
            for (int mt = 0; mt < 4; mt++)
#pragma unroll
                for (int nt = 0; nt < 8; nt++) {
                    MMA16816(acc[mt][nt], aH[mt], bH[nt]);
                    MMA16816(acc[mt][nt], aH[mt], bL[nt]);
                    MMA16816(acc[mt][nt], aL[mt], bH[nt]);
                }
        }
        __syncthreads();
    }

    // ---- epilogue ----
    const int crow = lane >> 2;
    const int ccol = (lane & 3) * 2;
#pragma unroll
    for (int mt = 0; mt < 4; mt++) {
#pragma unroll
        for (int nt = 0; nt < 8; nt++) {
            int n0 = bn + wn + nt * 8 + ccol;
            float b0 = bias[n0], b1 = bias[n0 + 1];
#pragma unroll
            for (int half = 0; half < 2; half++) {
                int m = bm + wm + mt * 16 + crow + half * 8;
                float v0 = acc[mt][nt][half * 2 + 0] + b0;
                float v1 = acc[mt][nt][half * 2 + 1] + b1;
                if (!permute) {
                    float2 v; v.x = v0; v.y = v1;
                    *(float2*)(Cf + (size_t)m * DM + n0) = v;
                } else {
                    int b_ = m >> 11;
                    int l  = m & (SEQ - 1);
                    int h  = n0 >> 6;
                    int d  = n0 & (HD - 1);
                    size_t idx = ((size_t)(b_ * NH + h) * SEQ + l) * HD + d;
                    uint32_t hh, ll;
                    cvt2_split(v0, v1, hh, ll);
                    *(uint32_t*)(Ch + idx) = hh;
                    *(uint32_t*)(Cl + idx) = ll;
                }
            }
        }
    }
}

// ====== Flash attention, cp.async 2-stage K/V pipeline (pre-split bf16) ====
// BM=128 q-rows/CTA (8 warps x 16 rows), BN=64 kv per tile.
#define APAD  72
#define AROW  (APAD * 2)           // 144 B row pitch
#define AQTI  (128 * AROW)         // 18432 B per Q buffer
#define AKTI  (64 * AROW)          // 9216 B per K/V buffer
#define KVST  (4 * AKTI)           // 36864 per stage (KH,KL,VH,VL)
#define A_QH  0
#define A_QL  (AQTI)
#define A_ST0 (2 * AQTI)
#define A_ST1 (2 * AQTI + KVST)
#define A_MS  (2 * AQTI + 2 * KVST)    // 2 x 64 floats
#define ATT_SMEM (A_MS + 512)          // 111104 B -> 2 CTAs/SM

__global__ __launch_bounds__(256) void attn_mma(
    const bf16* __restrict__ Qh, const bf16* __restrict__ Ql,
    const bf16* __restrict__ Kh, const bf16* __restrict__ Kl,
    const bf16* __restrict__ Vh, const bf16* __restrict__ Vl,
    const float* __restrict__ maskbias,
    bf16* __restrict__ Oh, bf16* __restrict__ Ol)
{
    extern __shared__ char smem[];
    const uint32_t sb = smem_u32(smem);
    float* Ms = (float*)(smem + A_MS);

    const int bh = blockIdx.y;
    const int b_ = bh >> 4;
    const int h  = bh & (NH - 1);
    const int q0 = blockIdx.x * 128;
    const int tid  = threadIdx.x;
    const int wid  = tid >> 5;
    const int lane = tid & 31;
    const int lr  = lane & 7;
    const int l8  = (lane >> 3) & 1;
    const int l16 = (lane >> 4) & 1;
    const int crow = lane >> 2;
    const int ccol = (lane & 3) * 2;
    const float scale = 0.125f;              // 1/sqrt(64)

    const bf16* kvsrc[4] = {Kh + (size_t)bh * SEQ * HD, Kl + (size_t)bh * SEQ * HD,
                            Vh + (size_t)bh * SEQ * HD, Vl + (size_t)bh * SEQ * HD};

    // issue cp.async K/V fill for one tile (2048 x 16B chunks, 8/thread)
    auto issueKV = [&](uint32_t stbase, int k0) {
#pragma unroll
        for (int i = 0; i < 8; i++) {
            int c = tid + i * 256;           // 0..2047
            int buf = c >> 9;
            int r   = (c >> 3) & 63;
            int seg = c & 7;
            const bf16* src = kvsrc[buf] + (size_t)(k0 + r) * HD + seg * 8;
            uint32_t dst = sb + stbase + buf * AKTI + r * AROW + seg * 16;
            CPA16(dst, src);
        }
        CPA_COMMIT();
    };

    issueKV(A_ST0, 0);                       // prefetch tile 0

    // ---- copy Q tile (128x64 bf16, hi+lo), plain loads ----
    {
        const bf16* srcs[2] = {Qh + ((size_t)bh * SEQ + q0) * HD,
                               Ql + ((size_t)bh * SEQ + q0) * HD};
        const uint32_t doff[2] = {A_QH, A_QL};
#pragma unroll
        for (int i = 0; i < 8; i++) {
            int c = tid + i * 256;           // 0..2047
            int buf = c >> 10;
            int r   = (c >> 3) & 127;
            int seg = c & 7;
            uint4 v = *(const uint4*)(srcs[buf] + r * HD + seg * 8);
            *(uint4*)(smem + doff[buf] + r * AROW + seg * 16) = v;
        }
    }

    float O[8][4];
#pragma unroll
    for (int i = 0; i < 8; i++)
#pragma unroll
        for (int j = 0; j < 4; j++) O[i][j] = 0.f;
    float m0 = -INFINITY, m1 = -INFINITY, li0 = 0.f, li1 = 0.f;

    const int NT = SEQ / 64;                 // 32
    for (int t = 0; t < NT; t++) {
        if (t + 1 < NT) { issueKV((t & 1) ? A_ST0 : A_ST1, (t + 1) * 64); CPA_WAIT1(); }
        else            { CPA_WAIT0(); }
        const uint32_t st = sb + ((t & 1) ? A_ST1 : A_ST0);
        const int msb = (t & 1) * 64;
        if (tid < 64) Ms[msb + tid] = maskbias[(size_t)b_ * SEQ + t * 64 + tid];
        __syncthreads();

        // ---- S = Q * K^T (warp: 16 q-rows x 64 kv) ----
        float S[8][4];
#pragma unroll
        for (int i = 0; i < 8; i++)
#pragma unroll
            for (int j = 0; j < 4; j++) S[i][j] = 0.f;

#pragma unroll
        for (int ks = 0; ks < 4; ks++) {
            uint32_t aH[4], aL[4];
            uint32_t offa = (uint32_t)(wid * 16 + lr + l8 * 8) * AROW
                          + (uint32_t)(ks * 16 + l16 * 8) * 2;
            LDMX4(aH[0], aH[1], aH[2], aH[3], sb + A_QH + offa);
            LDMX4(aL[0], aL[1], aL[2], aL[3], sb + A_QL + offa);
            uint32_t bH[8][2], bL[8][2];
#pragma unroll
            for (int np = 0; np < 4; np++) {
                uint32_t offb = (uint32_t)(np * 16 + lr + l16 * 8) * AROW
                              + (uint32_t)(ks * 16 + l8 * 8) * 2;
                uint32_t r0, r1, r2, r3;
                LDMX4(r0, r1, r2, r3, st + 0 * AKTI + offb);
                bH[np * 2][0] = r0; bH[np * 2][1] = r1;
                bH[np * 2 + 1][0] = r2; bH[np * 2 + 1][1] = r3;
                LDMX4(r0, r1, r2, r3, st + 1 * AKTI + offb);
                bL[np * 2][0] = r0; bL[np * 2][1] = r1;
                bL[np * 2 + 1][0] = r2; bL[np * 2 + 1][1] = r3;
            }
#pragma unroll
            for (int nt = 0; nt < 8; nt++) {
                MMA16816(S[nt], aH, bH[nt]);
                MMA16816(S[nt], aH, bL[nt]);
                MMA16816(S[nt], aL, bH[nt]);
            }
        }

        // ---- softmax ----
        float rm0 = -INFINITY, rm1 = -INFINITY;
#pragma unroll
        for (int nt = 0; nt < 8; nt++) {
            float mk0 = Ms[msb + nt * 8 + ccol], mk1 = Ms[msb + nt * 8 + ccol + 1];
            S[nt][0] = S[nt][0] * scale + mk0;
            S[nt][1] = S[nt][1] * scale + mk1;
            S[nt][2] = S[nt][2] * scale + mk0;
            S[nt][3] = S[nt][3] * scale + mk1;
            rm0 = fmaxf(rm0, fmaxf(S[nt][0], S[nt][1]));
            rm1 = fmaxf(rm1, fmaxf(S[nt][2], S[nt][3]));
        }
        rm0 = fmaxf(rm0, __shfl_xor_sync(0xffffffffu, rm0, 1));
        rm0 = fmaxf(rm0, __shfl_xor_sync(0xffffffffu, rm0, 2));
        rm1 = fmaxf(rm1, __shfl_xor_sync(0xffffffffu, rm1, 1));
        rm1 = fmaxf(rm1, __shfl_xor_sync(0xffffffffu, rm1, 2));

        float mn0 = fmaxf(m0, rm0), mn1 = fmaxf(m1, rm1);
        float ms0 = fmaxf(mn0, -1e30f), ms1 = fmaxf(mn1, -1e30f);
        float al0 = __expf(m0 - ms0), al1 = __expf(m1 - ms1);
        m0 = mn0; m1 = mn1;

        float rs0 = 0.f, rs1 = 0.f;
        uint32_t pH[4][4], pL[4][4];
#pragma unroll
        for (int nt = 0; nt < 8; nt++) {
            float p0 = __expf(S[nt][0] - ms0);
            float p1 = __expf(S[nt][1] - ms0);
            float p2 = __expf(S[nt][2] - ms1);
            float p3 = __expf(S[nt][3] - ms1);
            rs0 += p0 + p1; rs1 += p2 + p3;
            int ks2 = nt >> 1, base = (nt & 1) * 2;
            uint32_t h01, l01, h23, l23;
            cvt2_split(p0, p1, h01, l01);
            cvt2_split(p2, p3, h23, l23);
            pH[ks2][base] = h01; pH[ks2][base + 1] = h23;
            pL[ks2][base] = l01; pL[ks2][base + 1] = l23;
        }
        rs0 += __shfl_xor_sync(0xffffffffu, rs0, 1);
        rs0 += __shfl_xor_sync(0xffffffffu, rs0, 2);
        rs1 += __shfl_xor_sync(0xffffffffu, rs1, 1);
        rs1 += __shfl_xor_sync(0xffffffffu, rs1, 2);
        li0 = li0 * al0 + rs0;
        li1 = li1 * al1 + rs1;
#pragma unroll
        for (int nt = 0; nt < 8; nt++) {
            O[nt][0] *= al0; O[nt][1] *= al0;
            O[nt][2] *= al1; O[nt][3] *= al1;
        }

        // ---- O += P * V (V via ldmatrix.trans) ----
#pragma unroll
        for (int ks2 = 0; ks2 < 4; ks2++) {
            uint32_t bH2[8][2], bL2[8][2];
#pragma unroll
            for (int np = 0; np < 4; np++) {
                uint32_t offv = (uint32_t)(ks2 * 16 + lr + l8 * 8) * AROW
                              + (uint32_t)(np * 16 + l16 * 8) * 2;
                uint32_t r0, r1, r2, r3;
                LDMX4T(r0, r1, r2, r3, st + 2 * AKTI + offv);
                bH2[np * 2][0] = r0; bH2[np * 2][1] = r1;
                bH2[np * 2 + 1][0] = r2; bH2[np * 2 + 1][1] = r3;
                LDMX4T(r0, r1, r2, r3, st + 3 * AKTI + offv);
                bL2[np * 2][0] = r0; bL2[np * 2][1] = r1;
                bL2[np * 2 + 1][0] = r2; bL2[np * 2 + 1][1] = r3;
            }
#pragma unroll
            for (int nt = 0; nt < 8; nt++) {
                MMA16816(O[nt], pH[ks2], bH2[nt]);
                MMA16816(O[nt], pH[ks2], bL2[nt]);
                MMA16816(O[nt], pL[ks2], bH2[nt]);
            }
        }
        __syncthreads();   // all warps done with stage before its next fill
    }

    // ---- normalize + split-write out[b][l][h*64 + d] ----
    float inv0 = 1.f / li0, inv1 = 1.f / li1;
    int l0 = q0 + wid * 16 + crow;
    size_t base0 = ((size_t)b_ * SEQ + l0) * DM + h * HD;
    size_t base1 = base0 + (size_t)8 * DM;
#pragma unroll
    for (int nt = 0; nt < 8; nt++) {
        int col = nt * 8 + ccol;
        uint32_t hh, ll;
        cvt2_split(O[nt][0] * inv0, O[nt][1] * inv0, hh, ll);
        *(uint32_t*)(Oh + base0 + col) = hh;
        *(uint32_t*)(Ol + base0 + col) = ll;
        cvt2_split(O[nt][2] * inv1, O[nt][3] * inv1, hh, ll);
        *(uint32_t*)(Oh + base1 + col) = hh;
        *(uint32_t*)(Ol + base1 + col) = ll;
    }
}

// ================================ launch ===================================
extern "C" void kernel_launch(void* const* d_in, const int* in_sizes, int n_in,
                              void* d_out, int out_size)
{
    const float* q    = (const float*)d_in[0];
    const float* k    = (const float*)d_in[1];
    const float* v    = (const float*)d_in[2];
    const void*  mask = (const void*)d_in[3];
    const float* Wq = (const float*)d_in[4];
    const float* bq = (const float*)d_in[5];
    const float* Wk = (const float*)d_in[6];
    const float* bk = (const float*)d_in[7];
    const float* Wv = (const float*)d_in[8];
    const float* bv = (const float*)d_in[9];
    const float* Wo = (const float*)d_in[10];
    const float* bo = (const float*)d_in[11];

    bf16 *xh, *xl, *wh, *wl;
    bf16 *Qh, *Ql, *Kh, *Kl, *Vh, *Vl, *Ah, *Al;
    float* pM;
    cudaGetSymbolAddress((void**)&xh, g_xh);
    cudaGetSymbolAddress((void**)&xl, g_xl);
    cudaGetSymbolAddress((void**)&wh, g_wh);
    cudaGetSymbolAddress((void**)&wl, g_wl);
    cudaGetSymbolAddress((void**)&Qh, g_Qh);
    cudaGetSymbolAddress((void**)&Ql, g_Ql);
    cudaGetSymbolAddress((void**)&Kh, g_Kh);
    cudaGetSymbolAddress((void**)&Kl, g_Kl);
    cudaGetSymbolAddress((void**)&Vh, g_Vh);
    cudaGetSymbolAddress((void**)&Vl, g_Vl);
    cudaGetSymbolAddress((void**)&Ah, g_Ah);
    cudaGetSymbolAddress((void**)&Al, g_Al);
    cudaGetSymbolAddress((void**)&pM, g_maskbias);

    cudaFuncSetAttribute(gemm_ps, cudaFuncAttributeMaxDynamicSharedMemorySize,
                         GSMEM);
    cudaFuncSetAttribute(attn_mma, cudaFuncAttributeMaxDynamicSharedMemorySize,
                         ATT_SMEM);

    mask_convert<<<1, 1024>>>(mask);

    // pre-split all fp32 operands into bf16 hi/lo (single launch)
    const size_t NX = (size_t)MTOT * DM;     // 4M
    const size_t NW = (size_t)DM * DM;       // 1M
    CvtJobs jobs;
    jobs.src[0] = q;  jobs.dh[0] = xh + 0 * NX; jobs.dl[0] = xl + 0 * NX;
    jobs.src[1] = k;  jobs.dh[1] = xh + 1 * NX; jobs.dl[1] = xl + 1 * NX;
    jobs.src[2] = v;  jobs.dh[2] = xh + 2 * NX; jobs.dl[2] = xl + 2 * NX;
    jobs.src[3] = Wq; jobs.dh[3] = wh + 0 * NW; jobs.dl[3] = wl + 0 * NW;
    jobs.src[4] = Wk; jobs.dh[4] = wh + 1 * NW; jobs.dl[4] = wl + 1 * NW;
    jobs.src[5] = Wv; jobs.dh[5] = wh + 2 * NW; jobs.dl[5] = wl + 2 * NW;
    jobs.src[6] = Wo; jobs.dh[6] = wh + 3 * NW; jobs.dl[6] = wl + 3 * NW;
    cvt_all<<<(CVT_TOT4 + 255) / 256, 256>>>(jobs);

    dim3 ggrid(DM / 256, MTOT / 128);       // (4, 32) = 128 CTAs = 1 wave
    gemm_ps<<<ggrid, 256, GSMEM>>>(xh + 0 * NX, xl + 0 * NX, wh + 0 * NW, wl + 0 * NW,
                                   bq, nullptr, Qh, Ql, 1);
    gemm_ps<<<ggrid, 256, GSMEM>>>(xh + 1 * NX, xl + 1 * NX, wh + 1 * NW, wl + 1 * NW,
                                   bk, nullptr, Kh, Kl, 1);
    gemm_ps<<<ggrid, 256, GSMEM>>>(xh + 2 * NX, xl + 2 * NX, wh + 2 * NW, wl + 2 * NW,
                                   bv, nullptr, Vh, Vl, 1);

    dim3 agrid(SEQ / 128, BH);              // (16, 32)
    attn_mma<<<agrid, 256, ATT_SMEM>>>(Qh, Ql, Kh, Kl, Vh, Vl, pM, Ah, Al);

    gemm_ps<<<ggrid, 256, GSMEM>>>(Ah, Al, wh + 3 * NW, wl + 3 * NW,
                                   bo, (float*)d_out, nullptr, nullptr, 0);
}